// round 9
// baseline (speedup 1.0000x reference)
#include <cuda_runtime.h>
#include <math.h>

#define SCALE1 0.17677669529663687f  // 32^-0.5

typedef unsigned long long u64;

// ---------------- f32x2 packed helpers --------------------------------------
__device__ __forceinline__ u64 ffma2(u64 a, u64 b, u64 c){
  u64 d; asm("fma.rn.f32x2 %0, %1, %2, %3;" : "=l"(d) : "l"(a), "l"(b), "l"(c));
  return d;
}
__device__ __forceinline__ u64 pk2(float x, float y){
  u64 r; asm("mov.b64 %0, {%1, %2};" : "=l"(r) : "f"(x), "f"(y));
  return r;
}
__device__ __forceinline__ float2 up2(u64 v){
  float2 f; asm("mov.b64 {%0, %1}, %2;" : "=f"(f.x), "=f"(f.y) : "l"(v));
  return f;
}

// ---------------- scratch (static device globals; no allocation) ------------
__device__ float g_proj1[16384*768];   // [q1 | q2 | kv2(k,v) | lepe_lin]
__device__ float g_xs_pre[4096*256];
__device__ float g_xs[4096*256];
__device__ float g_kv1[4096*256];
__device__ float g_cat[16384*256];     // [x1 | x2]
__device__ float g_pre[16384*256];     // cat + lepe
__device__ float g_part[4*512*1024];   // per-(h,qtile) partial key-prob sums
__device__ float g_gsum[4*1024];
__device__ float g_lm[4*4096];
__device__ float g_Wcat[256*768];
__device__ float g_bcat[768];
__device__ float g_srwT[1024*256];     // (seg*256+ic, oc)
__device__ float g_lwT[9*256];         // (tap, c)

// ---------------- helpers ---------------------------------------------------
__device__ __forceinline__ float wredmax(float v){
  #pragma unroll
  for(int o=16;o;o>>=1) v = fmaxf(v, __shfl_xor_sync(0xFFFFFFFFu, v, o));
  return v;
}
__device__ __forceinline__ float wredsum(float v){
  #pragma unroll
  for(int o=16;o;o>>=1) v += __shfl_xor_sync(0xFFFFFFFFu, v, o);
  return v;
}

// ---------------- weight prep ------------------------------------------------
__global__ void prep_k(const float* __restrict__ q1w, const float* __restrict__ q2w,
                       const float* __restrict__ kv2w, const float* __restrict__ lpw,
                       const float* __restrict__ q1b, const float* __restrict__ q2b,
                       const float* __restrict__ kv2b, const float* __restrict__ lpb,
                       const float* __restrict__ srw, const float* __restrict__ lcw)
{
  int i0 = blockIdx.x*blockDim.x + threadIdx.x;
  int st = gridDim.x*blockDim.x;
  for(int idx=i0; idx<256*768; idx+=st){
    int k = idx/768, c = idx%768;
    float v;
    if(c<128)      v = q1w[k*128+c];
    else if(c<256) v = q2w[k*128+c-128];
    else if(c<512) v = kv2w[k*256+c-256];
    else           v = lpw[k*256+c-512];
    g_Wcat[idx] = v;
  }
  for(int c=i0;c<768;c+=st)
    g_bcat[c] = (c<128)?q1b[c]:(c<256)?q2b[c-128]:(c<512)?kv2b[c-256]:lpb[c-512];
  for(int idx=i0; idx<1024*256; idx+=st){
    int k = idx>>8, oc = idx&255;
    int seg = k>>8, ic = k&255;
    g_srwT[idx] = srw[(oc*256+ic)*4 + seg];
  }
  for(int idx=i0; idx<9*256; idx+=st){
    int tap = idx>>8, c = idx&255;
    g_lwT[idx] = lcw[c*9+tap];
  }
}

// ---------------- 128x128 GEMM body, 256 thr, 8x8 micro, f32x2 --------------
// MODE 0: x(16384x256) @ g_Wcat(256x768)+g_bcat -> g_proj1
// MODE 1: gather-x(4096x1024) @ g_srwT(1024x256)+sr_b -> g_xs_pre
// MODE 2: g_xs(4096x256) @ kv1_w(256x256)+kv1_b -> g_kv1
// MODE 3: g_pre(16384x256) @ proj_w(256x256)+proj_b, x2 -> d_out
template<int MODE>
__device__ __forceinline__ void gemm_body(const float* __restrict__ A,
                                          const float* __restrict__ Bm,
                                          const float* __restrict__ bias,
                                          float* __restrict__ C,
                                          int by, int bx)
{
  constexpr int K  = (MODE==1)?1024:256;
  constexpr int Nn = (MODE==0)?768:256;
  __shared__ float sA[16][132];
  __shared__ float sB[16][132];
  int t = threadIdx.x;
  int row0 = by*128, col0 = bx*128;
  int lr = t>>1;          // A load row 0..127
  int lk = (t&1)*8;       // A k-offset
  int bk = t>>4;          // B row (k)
  int bn = (t&15)*8;      // B col offset
  int r16 = t>>4, c16 = t&15;
  u64 acc[8][4];
  #pragma unroll
  for(int i=0;i<8;i++)
    #pragma unroll
    for(int j=0;j<4;j++) acc[i][j] = 0ull;

  for(int kt=0; kt<K/16; kt++){
    int k0 = kt*16;
    float4 a0, a1;
    if constexpr (MODE==1){
      int r = row0+lr;
      int b = r>>10, p = r&1023, ii = p>>5, jj = p&31;
      int k = k0 + lk;
      int seg = k>>8, ic = k&255;
      int tok = ((2*ii + (seg>>1))<<6) + 2*jj + (seg&1);
      const float* ap = A + ((size_t)((b<<12)+tok))*256 + ic;
      a0 = *(const float4*)ap; a1 = *(const float4*)(ap+4);
    } else {
      const float* ap = A + (size_t)(row0+lr)*K + k0 + lk;
      a0 = *(const float4*)ap; a1 = *(const float4*)(ap+4);
    }
    const float* bp = Bm + (size_t)(k0+bk)*Nn + col0 + bn;
    float4 b0 = *(const float4*)bp;
    float4 b1 = *(const float4*)(bp+4);
    __syncthreads();
    sA[lk+0][lr]=a0.x; sA[lk+1][lr]=a0.y; sA[lk+2][lr]=a0.z; sA[lk+3][lr]=a0.w;
    sA[lk+4][lr]=a1.x; sA[lk+5][lr]=a1.y; sA[lk+6][lr]=a1.z; sA[lk+7][lr]=a1.w;
    *(float4*)&sB[bk][bn]   = b0;
    *(float4*)&sB[bk][bn+4] = b1;
    __syncthreads();
    #pragma unroll
    for(int kk=0;kk<16;kk++){
      float4 av0 = *(const float4*)&sA[kk][r16*8];
      float4 av1 = *(const float4*)&sA[kk][r16*8+4];
      ulonglong2 bb0 = *(const ulonglong2*)&sB[kk][c16*4];
      ulonglong2 bb1 = *(const ulonglong2*)&sB[kk][64 + c16*4];
      float ar[8] = {av0.x,av0.y,av0.z,av0.w,av1.x,av1.y,av1.z,av1.w};
      u64 bp4[4] = {bb0.x, bb0.y, bb1.x, bb1.y};
      #pragma unroll
      for(int i=0;i<8;i++){
        u64 ad = pk2(ar[i], ar[i]);
        #pragma unroll
        for(int j=0;j<4;j++) acc[i][j] = ffma2(ad, bp4[j], acc[i][j]);
      }
    }
  }
  // epilogue
  #pragma unroll
  for(int i=0;i<8;i++){
    int r = row0 + r16*8 + i;
    #pragma unroll
    for(int g=0; g<2; g++){
      int c = col0 + g*64 + c16*4;
      float2 p0 = up2(acc[i][g*2+0]);
      float2 p1 = up2(acc[i][g*2+1]);
      float4 v;
      v.x = p0.x + bias[c+0]; v.y = p0.y + bias[c+1];
      v.z = p1.x + bias[c+2]; v.w = p1.y + bias[c+3];
      if constexpr (MODE==3){ v.x*=2.f; v.y*=2.f; v.z*=2.f; v.w*=2.f; }
      *(float4*)&C[(size_t)r*Nn + c] = v;
    }
  }
}

// fused launch: blocks [0,768) = mode0 (6x128), [768,832) = mode1 (2x32)
__global__ void gemm01_k(const float* __restrict__ x, const float* __restrict__ srb){
  int bid = blockIdx.x;
  if(bid < 768) gemm_body<0>(x, g_Wcat, g_bcat, g_proj1, bid/6, bid%6);
  else { int b2 = bid-768; gemm_body<1>(x, g_srwT, srb, g_xs_pre, b2>>1, b2&1); }
}
__global__ void gemm2_k(const float* __restrict__ kv1w, const float* __restrict__ kv1b){
  gemm_body<2>(g_xs, kv1w, kv1b, g_kv1, blockIdx.x>>1, blockIdx.x&1);
}
__global__ void gemm3_k(const float* __restrict__ pw, const float* __restrict__ pb,
                        float* __restrict__ out){
  gemm_body<3>(g_pre, pw, pb, out, blockIdx.x>>1, blockIdx.x&1);
}

// ---------------- LayerNorm + exact GELU ------------------------------------
__global__ void ln_gelu_k(const float* __restrict__ nw, const float* __restrict__ nb){
  int r = blockIdx.x, c = threadIdx.x;
  float v = g_xs_pre[(size_t)r*256+c];
  float s = v, s2 = v*v;
  #pragma unroll
  for(int o=16;o;o>>=1){ s += __shfl_xor_sync(~0u,s,o); s2 += __shfl_xor_sync(~0u,s2,o); }
  __shared__ float rs[8], rs2[8];
  int w = c>>5, l = c&31;
  if(l==0){ rs[w]=s; rs2[w]=s2; }
  __syncthreads();
  if(w==0){
    float a=(l<8)?rs[l]:0.f, a2=(l<8)?rs2[l]:0.f;
    #pragma unroll
    for(int o=4;o;o>>=1){ a+=__shfl_xor_sync(~0u,a,o); a2+=__shfl_xor_sync(~0u,a2,o); }
    if(l==0){ rs[0]=a; rs2[0]=a2; }
  }
  __syncthreads();
  float m  = rs[0]*(1.f/256.f);
  float var= rs2[0]*(1.f/256.f) - m*m;
  float y  = (v-m)*rsqrtf(var+1e-5f)*nw[c] + nb[c];
  g_xs[(size_t)r*256+c] = 0.5f*y*(1.f+erff(y*0.70710678118f));
}

// ---------------- branch-1 attention (full score row in smem, f32x2) --------
// grid (128 qtiles, 4 heads, 4 batch), 256 threads, dyn smem 155136 B
extern __shared__ float dsm[];
__global__ void attn1_k(){
  float* sS  = dsm;              // 32*1032 = 33024
  float* sQ  = sS + 33024;       // 32*36   = 1152
  float* sKV = sQ + 1152;        // 128*36  = 4608
  int t = threadIdx.x;
  int qt = blockIdx.x, h = blockIdx.y, b = blockIdx.z;
  int n0 = qt*32;
  // load Q (32x32) as float4, stride-36 rows
  {
    int q = t>>3, d4 = (t&7)*4;
    *(float4*)&sQ[q*36+d4] =
      *(const float4*)&g_proj1[((size_t)(b*4096+n0+q))*768 + h*32 + d4];
  }
  int qb = t>>5, kb = t&31;
  for(int kt=0;kt<8;kt++){
    int m0 = kt<<7;
    __syncthreads();
    for(int e=t; e<1024; e+=256){
      int mm = e>>3, d4 = (e&7)*4;
      *(float4*)&sKV[mm*36+d4] =
        *(const float4*)&g_kv1[((size_t)(b*1024+m0+mm))*256 + h*32 + d4];
    }
    __syncthreads();
    u64 acc2[4][4] = {};
    #pragma unroll
    for(int d4=0; d4<8; d4++){
      ulonglong2 qv[4], kv[4];
      #pragma unroll
      for(int i=0;i<4;i++) qv[i] = *(const ulonglong2*)&sQ[(qb*4+i)*36 + d4*4];
      #pragma unroll
      for(int u=0;u<4;u++) kv[u] = *(const ulonglong2*)&sKV[(kb+32*u)*36 + d4*4];
      #pragma unroll
      for(int i=0;i<4;i++)
        #pragma unroll
        for(int u=0;u<4;u++){
          acc2[i][u] = ffma2(qv[i].x, kv[u].x, acc2[i][u]);
          acc2[i][u] = ffma2(qv[i].y, kv[u].y, acc2[i][u]);
        }
    }
    #pragma unroll
    for(int i=0;i<4;i++)
      #pragma unroll
      for(int u=0;u<4;u++){
        float2 pr = up2(acc2[i][u]);
        sS[(qb*4+i)*1032 + m0 + kb + 32*u] = (pr.x+pr.y)*SCALE1;
      }
  }
  __syncthreads();
  // softmax: warp w -> queries w*4..w*4+3, float4 over keys
  {
    int w = t>>5, l = t&31;
    for(int qi=0;qi<4;qi++){
      float4* row4 = (float4*)(sS + (w*4+qi)*1032);
      float mx = -1e30f;
      #pragma unroll
      for(int i2=0;i2<8;i2++){
        float4 v = row4[l + 32*i2];
        mx = fmaxf(mx, fmaxf(fmaxf(v.x,v.y), fmaxf(v.z,v.w)));
      }
      mx = wredmax(mx);
      float sm = 0.f;
      #pragma unroll
      for(int i2=0;i2<8;i2++){
        float4 v = row4[l + 32*i2];
        v.x = __expf(v.x-mx); v.y = __expf(v.y-mx);
        v.z = __expf(v.z-mx); v.w = __expf(v.w-mx);
        row4[l+32*i2] = v;
        sm += (v.x+v.y)+(v.z+v.w);
      }
      sm = wredsum(sm);
      float inv = 1.f/sm;
      #pragma unroll
      for(int i2=0;i2<8;i2++){
        float4 v = row4[l+32*i2];
        v.x*=inv; v.y*=inv; v.z*=inv; v.w*=inv;
        row4[l+32*i2] = v;
      }
    }
  }
  __syncthreads();
  // per-key partial sums for g (float4 over m)
  {
    float4 s4 = make_float4(0.f,0.f,0.f,0.f);
    #pragma unroll 8
    for(int q=0;q<32;q++){
      float4 v = *(const float4*)&sS[q*1032 + t*4];
      s4.x+=v.x; s4.y+=v.y; s4.z+=v.z; s4.w+=v.w;
    }
    *(float4*)&g_part[((size_t)(b*512 + h*128 + qt))*1024 + t*4] = s4;
  }
  // AV: thread = (kq: 8 groups x16 keys, qb2: 8 groups x4 q, db: 4 groups x8 dd)
  int kq = t>>5;
  int qb2 = (t>>2)&7;
  int db = t&3;
  u64 accv[4][4] = {};
  for(int kt=0;kt<8;kt++){
    int m0 = kt<<7;
    __syncthreads();
    for(int e=t; e<1024; e+=256){
      int mm = e>>3, d4 = (e&7)*4;
      *(float4*)&sKV[mm*36+d4] =
        *(const float4*)&g_kv1[((size_t)(b*1024+m0+mm))*256 + 128 + h*32 + d4];
    }
    __syncthreads();
    #pragma unroll
    for(int mm2=0;mm2<16;mm2++){
      int mm = kq*16+mm2;
      ulonglong2 v01 = *(const ulonglong2*)&sKV[mm*36 + db*8];
      ulonglong2 v23 = *(const ulonglong2*)&sKV[mm*36 + db*8 + 4];
      #pragma unroll
      for(int i=0;i<4;i++){
        float p = sS[(qb2*4+i)*1032 + m0 + mm];
        u64 pd = pk2(p,p);
        accv[i][0] = ffma2(pd, v01.x, accv[i][0]);
        accv[i][1] = ffma2(pd, v01.y, accv[i][1]);
        accv[i][2] = ffma2(pd, v23.x, accv[i][2]);
        accv[i][3] = ffma2(pd, v23.y, accv[i][3]);
      }
    }
  }
  __syncthreads();   // all prob reads done; reuse sS as reduction scratch
  #pragma unroll
  for(int i=0;i<4;i++){
    float2 a0 = up2(accv[i][0]), a1 = up2(accv[i][1]);
    float2 a2 = up2(accv[i][2]), a3 = up2(accv[i][3]);
    float* dst = sS + kq*1024 + (qb2*4+i)*32 + db*8;
    float4 w0 = make_float4(a0.x,a0.y,a1.x,a1.y);
    float4 w1 = make_float4(a2.x,a2.y,a3.x,a3.y);
    *(float4*)&dst[0] = w0;
    *(float4*)&dst[4] = w1;
  }
  __syncthreads();
  {
    float4 s4 = make_float4(0.f,0.f,0.f,0.f);
    #pragma unroll
    for(int g=0; g<8; g++){
      float4 v = *(const float4*)&sS[g*1024 + t*4];
      s4.x+=v.x; s4.y+=v.y; s4.z+=v.z; s4.w+=v.w;
    }
    int oi = t*4;
    int q = oi>>5, dd = oi&31;
    *(float4*)&g_cat[((size_t)(b*4096+n0+q))*256 + h*32 + dd] = s4;
  }
}

// ---------------- g reduction (64 blocks, deterministic) ---------------------
__global__ void gred_k(){
  int b = blockIdx.x>>4;
  int ml = threadIdx.x&63;
  int pg = threadIdx.x>>6;
  int m = (blockIdx.x&15)*64 + ml;
  float s = 0.f;
  for(int p=pg; p<512; p+=4)
    s += g_part[((size_t)(b*512+p))*1024 + m];
  __shared__ float red[4][64];
  red[pg][ml] = s;
  __syncthreads();
  if(pg==0)
    g_gsum[b*1024+m] = (red[0][ml]+red[1][ml])+(red[2][ml]+red[3][ml]);
}

// ---------------- branch-2 window attention ----------------------------------
__global__ void attn2_k(){
  __shared__ float sQ[4][16][33], sK[4][16][33], sV[4][16][33];
  __shared__ float sS[4][16][17];
  int t = threadIdx.x;
  int win = blockIdx.x, b = blockIdx.y;
  int i1 = win>>4, j1 = win&15;
  for(int e=t;e<2048;e+=256){
    int h=e>>9, rem=e&511, tk=rem>>5, dd=rem&31;
    int n = ((i1*4 + (tk>>2))<<6) + j1*4 + (tk&3);
    size_t base = ((size_t)(b*4096+n))*768 + h*32+dd;
    sQ[h][tk][dd] = g_proj1[base+128];
    sK[h][tk][dd] = g_proj1[base+256];
    sV[h][tk][dd] = g_proj1[base+384];
  }
  __syncthreads();
  int h = t>>6, q = (t>>2)&15, kg = t&3;
  #pragma unroll
  for(int k2=0;k2<4;k2++){
    int kk = kg*4+k2;
    float s = 0.f;
    #pragma unroll
    for(int dd=0;dd<32;dd++) s = fmaf(sQ[h][q][dd], sK[h][kk][dd], s);
    sS[h][q][kk] = s*SCALE1;
  }
  __syncthreads();
  if(kg==0){
    float* row = sS[h][q];
    float mx=-1e30f;
    #pragma unroll
    for(int kk=0;kk<16;kk++) mx = fmaxf(mx,row[kk]);
    float sm=0.f;
    #pragma unroll
    for(int kk=0;kk<16;kk++){ float p=__expf(row[kk]-mx); row[kk]=p; sm+=p; }
    float inv=1.f/sm;
    #pragma unroll
    for(int kk=0;kk<16;kk++) row[kk]*=inv;
  }
  __syncthreads();
  float acc[8]={};
  int dd0 = kg*8;
  #pragma unroll
  for(int kk=0;kk<16;kk++){
    float p = sS[h][q][kk];
    #pragma unroll
    for(int u=0;u<8;u++) acc[u] = fmaf(p, sV[h][kk][dd0+u], acc[u]);
  }
  {
    int n = ((i1*4+(q>>2))<<6) + j1*4 + (q&3);
    float* dst = &g_cat[((size_t)(b*4096+n))*256 + 128 + h*32 + dd0];
    #pragma unroll
    for(int u=0;u<8;u++) dst[u] = acc[u];
  }
  if(t<16){
    float s=0.f;
    #pragma unroll
    for(int h2=0;h2<4;h2++)
      #pragma unroll
      for(int q2=0;q2<16;q2++) s += sS[h2][q2][t];
    int y = i1*4 + (t>>2), x = j1*4 + (t&3);
    g_lm[b*4096 + y*64 + x] = s*(1.f/64.f);
  }
}

// ---------------- depthwise lepe conv + concat add ---------------------------
__global__ void lepe_k(const float* __restrict__ lcb){
  int blk = blockIdx.x, c = threadIdx.x;
  int b = blk>>12, pos = blk&4095, y = pos>>6, x = pos&63;
  float acc = lcb[c];
  #pragma unroll
  for(int dy=-1;dy<=1;dy++){
    int yy = y+dy; if((unsigned)yy >= 64u) continue;
    #pragma unroll
    for(int dx=-1;dx<=1;dx++){
      int xx = x+dx; if((unsigned)xx >= 64u) continue;
      int tap = (dy+1)*3 + (dx+1);
      acc = fmaf(g_proj1[((size_t)(b*4096 + yy*64+xx))*768 + 512 + c],
                 g_lwT[tap*256+c], acc);
    }
  }
  size_t o = (size_t)blk*256 + c;
  g_pre[o] = g_cat[o] + acc;
}

// ---------------- mask assembly ----------------------------------------------
__global__ void mask_k(float* __restrict__ out){
  int idx = blockIdx.x*256 + threadIdx.x;      // 0..16383
  int b = idx>>12, pos = idx&4095, y = pos>>6, x = pos&63;
  float v = g_lm[idx] + g_gsum[b*1024 + (y>>1)*32 + (x>>1)] * (1.f/16384.f);
  out[4194304 + idx] = v;                       // mask1 [b, y*64+x]
  out[4210688 + b*4096 + x*64 + y] = v;         // mask2 [b, x*64+y]
}

// ---------------- launch -----------------------------------------------------
extern "C" void kernel_launch(void* const* d_in, const int* in_sizes, int n_in,
                              void* d_out, int out_size)
{
  const float* x    = (const float*)d_in[0];
  const float* q1w  = (const float*)d_in[1];
  const float* q1b  = (const float*)d_in[2];
  const float* kv1w = (const float*)d_in[3];
  const float* kv1b = (const float*)d_in[4];
  const float* q2w  = (const float*)d_in[5];
  const float* q2b  = (const float*)d_in[6];
  const float* kv2w = (const float*)d_in[7];
  const float* kv2b = (const float*)d_in[8];
  const float* lpw  = (const float*)d_in[9];
  const float* lpb  = (const float*)d_in[10];
  const float* lcw  = (const float*)d_in[11];
  const float* lcb  = (const float*)d_in[12];
  const float* srw  = (const float*)d_in[13];
  const float* srb  = (const float*)d_in[14];
  const float* nw   = (const float*)d_in[15];
  const float* nb   = (const float*)d_in[16];
  const float* pw   = (const float*)d_in[17];
  const float* pb   = (const float*)d_in[18];
  float* out = (float*)d_out;

  const int ATTN1_SMEM = (33024 + 1152 + 4608) * 4;  // 155136 B
  cudaFuncSetAttribute(attn1_k, cudaFuncAttributeMaxDynamicSharedMemorySize, ATTN1_SMEM);

  prep_k<<<256,256>>>(q1w,q2w,kv2w,lpw,q1b,q2b,kv2b,lpb,srw,lcw);
  gemm01_k<<<832,256>>>(x, srb);                 // proj1 + xs_pre fused
  attn2_k<<<dim3(256,4),256>>>();
  ln_gelu_k<<<4096,256>>>(nw, nb);
  gemm2_k<<<64,256>>>(kv1w, kv1b);               // kv1
  attn1_k<<<dim3(128,4,4), 256, ATTN1_SMEM>>>();
  gred_k<<<64,256>>>();
  lepe_k<<<16384,256>>>(lcb);
  gemm3_k<<<256,256>>>(pw, pb, out);             // proj -> out
  mask_k<<<64,256>>>(out);
}

// round 10
// speedup vs baseline: 1.7018x; 1.7018x over previous
#include <cuda_runtime.h>
#include <math.h>

#define SCALE1 0.17677669529663687f  // 32^-0.5

// ---------------- scratch (static device globals; no allocation) ------------
__device__ float g_proj1[16384*768];   // [q1 | q2 | kv2(k,v) | lepe_lin]
__device__ float g_xs_pre[4096*256];
__device__ float g_xs[4096*256];
__device__ float g_kv1[4096*256];
__device__ float g_cat[16384*256];     // [x1 | x2]
__device__ float g_pre[16384*256];     // cat + lepe
__device__ float g_part[4*512*1024];   // per-(h,qtile) partial key-prob sums
__device__ float g_gsum[4*1024];
__device__ float g_lm[4*4096];
__device__ float g_Wcat[256*768];
__device__ float g_bcat[768];
__device__ float g_srwT[1024*256];     // (seg*256+ic, oc)
__device__ float g_lwT[9*256];         // (tap, c)

// ---------------- helpers ---------------------------------------------------
__device__ __forceinline__ float wredmax(float v){
  #pragma unroll
  for(int o=16;o;o>>=1) v = fmaxf(v, __shfl_xor_sync(0xFFFFFFFFu, v, o));
  return v;
}
__device__ __forceinline__ float wredsum(float v){
  #pragma unroll
  for(int o=16;o;o>>=1) v += __shfl_xor_sync(0xFFFFFFFFu, v, o);
  return v;
}

// ---------------- weight prep ------------------------------------------------
__global__ void prep_k(const float* __restrict__ q1w, const float* __restrict__ q2w,
                       const float* __restrict__ kv2w, const float* __restrict__ lpw,
                       const float* __restrict__ q1b, const float* __restrict__ q2b,
                       const float* __restrict__ kv2b, const float* __restrict__ lpb,
                       const float* __restrict__ srw, const float* __restrict__ lcw)
{
  int i0 = blockIdx.x*blockDim.x + threadIdx.x;
  int st = gridDim.x*blockDim.x;
  for(int idx=i0; idx<256*768; idx+=st){
    int k = idx/768, c = idx%768;
    float v;
    if(c<128)      v = q1w[k*128+c];
    else if(c<256) v = q2w[k*128+c-128];
    else if(c<512) v = kv2w[k*256+c-256];
    else           v = lpw[k*256+c-512];
    g_Wcat[idx] = v;
  }
  for(int c=i0;c<768;c+=st)
    g_bcat[c] = (c<128)?q1b[c]:(c<256)?q2b[c-128]:(c<512)?kv2b[c-256]:lpb[c-512];
  for(int idx=i0; idx<1024*256; idx+=st){
    int k = idx>>8, oc = idx&255;
    int seg = k>>8, ic = k&255;
    g_srwT[idx] = srw[(oc*256+ic)*4 + seg];
  }
  for(int idx=i0; idx<9*256; idx+=st){
    int tap = idx>>8, c = idx&255;
    g_lwT[idx] = lcw[c*9+tap];
  }
}

// ---------------- 64x64 tiled GEMM body, 256 thr, 4x4 micro (R7-proven) -----
// MODE 0: x(16384x256) @ g_Wcat(256x768)+g_bcat -> g_proj1
// MODE 1: gather-x(4096x1024) @ g_srwT(1024x256)+sr_b -> g_xs_pre
// MODE 2: g_xs(4096x256) @ kv1_w(256x256)+kv1_b -> g_kv1
// MODE 3: g_pre(16384x256) @ proj_w(256x256)+proj_b, x2 -> d_out
template<int MODE>
__device__ __forceinline__ void gemm_body(const float* __restrict__ A,
                                          const float* __restrict__ B,
                                          const float* __restrict__ bi,
                                          float* __restrict__ C,
                                          int by, int bx)
{
  constexpr int K  = (MODE==1)?1024:256;
  constexpr int Nn = (MODE==0)?768:256;
  __shared__ float sA[16][68];
  __shared__ float sB[16][68];
  int t = threadIdx.x;
  int row0 = by*64, col0 = bx*64;
  int la_m = t>>2, la_k = (t&3)<<2;
  int lb_k = t>>4, lb_n = (t&15)<<2;
  int tr = (t>>4)<<2, tc = (t&15)<<2;
  float acc[4][4] = {};
  for(int kt=0; kt<(K>>4); kt++){
    float4 a4;
    if(MODE==1){
      int r = row0+la_m;
      int b = r>>10, p = r&1023, i = p>>5, j = p&31;
      int k = (kt<<4)+la_k;
      int seg = k>>8, ic = k&255;
      int tok = ((2*i + (seg>>1))<<6) + 2*j + (seg&1);
      a4 = *(const float4*)(A + (size_t)((b<<12)+tok)*256 + ic);
    } else {
      a4 = *(const float4*)(A + (size_t)(row0+la_m)*K + (kt<<4)+la_k);
    }
    float4 b4 = *(const float4*)(B + (size_t)((kt<<4)+lb_k)*Nn + col0+lb_n);
    __syncthreads();
    sA[la_k][la_m]=a4.x; sA[la_k+1][la_m]=a4.y;
    sA[la_k+2][la_m]=a4.z; sA[la_k+3][la_m]=a4.w;
    *(float4*)&sB[lb_k][lb_n] = b4;
    __syncthreads();
    #pragma unroll
    for(int kk=0;kk<16;kk++){
      float4 av=*(const float4*)&sA[kk][tr];
      float4 bv=*(const float4*)&sB[kk][tc];
      float ar[4]={av.x,av.y,av.z,av.w}, br[4]={bv.x,bv.y,bv.z,bv.w};
      #pragma unroll
      for(int i=0;i<4;i++)
        #pragma unroll
        for(int j=0;j<4;j++) acc[i][j] = fmaf(ar[i],br[j],acc[i][j]);
    }
  }
  #pragma unroll
  for(int i=0;i<4;i++){
    int r = row0+tr+i;
    float4 v4;
    v4.x = acc[i][0]+bi[col0+tc+0];
    v4.y = acc[i][1]+bi[col0+tc+1];
    v4.z = acc[i][2]+bi[col0+tc+2];
    v4.w = acc[i][3]+bi[col0+tc+3];
    if(MODE==3){ v4.x*=2.f; v4.y*=2.f; v4.z*=2.f; v4.w*=2.f; }
    *(float4*)&C[(size_t)r*Nn + col0+tc] = v4;
  }
}

// fused: blocks [0,3072) = mode0 (256x12 tiles), [3072,3328) = mode1 (64x4)
__global__ void gemm01_k(const float* __restrict__ x, const float* __restrict__ srb){
  int bid = blockIdx.x;
  if(bid < 3072) gemm_body<0>(x, g_Wcat, g_bcat, g_proj1, bid/12, bid%12);
  else { int b2 = bid-3072; gemm_body<1>(x, g_srwT, srb, g_xs_pre, b2>>2, b2&3); }
}
__global__ void gemm2_k(const float* __restrict__ kv1w, const float* __restrict__ kv1b){
  gemm_body<2>(g_xs, kv1w, kv1b, g_kv1, blockIdx.x>>2, blockIdx.x&3);
}
__global__ void gemm3_k(const float* __restrict__ pw, const float* __restrict__ pb,
                        float* __restrict__ out){
  gemm_body<3>(g_pre, pw, pb, out, blockIdx.x>>2, blockIdx.x&3);
}

// ---------------- LayerNorm + exact GELU ------------------------------------
__global__ void ln_gelu_k(const float* __restrict__ nw, const float* __restrict__ nb){
  int r = blockIdx.x, c = threadIdx.x;
  float v = g_xs_pre[(size_t)r*256+c];
  float s = v, s2 = v*v;
  #pragma unroll
  for(int o=16;o;o>>=1){ s += __shfl_xor_sync(~0u,s,o); s2 += __shfl_xor_sync(~0u,s2,o); }
  __shared__ float rs[8], rs2[8];
  int w = c>>5, l = c&31;
  if(l==0){ rs[w]=s; rs2[w]=s2; }
  __syncthreads();
  if(w==0){
    float a=(l<8)?rs[l]:0.f, a2=(l<8)?rs2[l]:0.f;
    #pragma unroll
    for(int o=4;o;o>>=1){ a+=__shfl_xor_sync(~0u,a,o); a2+=__shfl_xor_sync(~0u,a2,o); }
    if(l==0){ rs[0]=a; rs2[0]=a2; }
  }
  __syncthreads();
  float m  = rs[0]*(1.f/256.f);
  float var= rs2[0]*(1.f/256.f) - m*m;
  float y  = (v-m)*rsqrtf(var+1e-5f)*nw[c] + nb[c];
  g_xs[(size_t)r*256+c] = 0.5f*y*(1.f+erff(y*0.70710678118f));
}

// ---------------- branch-1 attention ----------------------------------------
// grid (128 qtiles, 4 heads, 4 batch), 256 threads
// dyn smem: sS 32*1032 + sQ 32*36 + sKV double buffer 2*128*36  floats
extern __shared__ float dsm[];
__global__ void attn1_k(){
  float* sS  = dsm;               // 33024 floats
  float* sQ  = sS + 33024;        // 1152
  float* sKV = sQ + 1152;         // 2 * 4608
  int t = threadIdx.x;
  int qt = blockIdx.x, h = blockIdx.y, b = blockIdx.z;
  int n0 = qt*32;
  // per-thread tile-fetch coordinates (4 float4 per thread = 128x32 tile)
  int fm[4], fd[4];
  #pragma unroll
  for(int r=0;r<4;r++){ int e = t + 256*r; fm[r] = e>>3; fd[r] = (e&7)<<2; }
  size_t kvbase = (size_t)(b<<10)*256;

  // load Q (32x32), 1 float4/thread
  {
    int q = t>>3, d4 = (t&7)<<2;
    *(float4*)&sQ[q*36+d4] =
      *(const float4*)&g_proj1[((size_t)(b*4096+n0+q))*768 + h*32 + d4];
  }
  float4 pf[4];
  #pragma unroll
  for(int r=0;r<4;r++)
    pf[r] = *(const float4*)&g_kv1[kvbase + (size_t)fm[r]*256 + h*32 + fd[r]];
  __syncthreads();
  #pragma unroll
  for(int r=0;r<4;r++) *(float4*)&sKV[fm[r]*36 + fd[r]] = pf[r];
  __syncthreads();

  // ---- scores ----
  int qb = t>>5, kb = t&31;
  for(int kt=0;kt<8;kt++){
    float* buf = sKV + (kt&1)*4608;
    if(kt<7){
      #pragma unroll
      for(int r=0;r<4;r++)
        pf[r] = *(const float4*)&g_kv1[kvbase + (size_t)(((kt+1)<<7)+fm[r])*256 + h*32 + fd[r]];
    }
    float acc[4][4] = {};
    #pragma unroll
    for(int d4=0; d4<8; d4++){
      float4 qv[4], kv[4];
      #pragma unroll
      for(int i=0;i<4;i++) qv[i] = *(const float4*)&sQ[(qb*4+i)*36 + (d4<<2)];
      #pragma unroll
      for(int u=0;u<4;u++) kv[u] = *(const float4*)&buf[(kb+32*u)*36 + (d4<<2)];
      #pragma unroll
      for(int i=0;i<4;i++)
        #pragma unroll
        for(int u=0;u<4;u++){
          acc[i][u] = fmaf(qv[i].x, kv[u].x, acc[i][u]);
          acc[i][u] = fmaf(qv[i].y, kv[u].y, acc[i][u]);
          acc[i][u] = fmaf(qv[i].z, kv[u].z, acc[i][u]);
          acc[i][u] = fmaf(qv[i].w, kv[u].w, acc[i][u]);
        }
    }
    int m0 = kt<<7;
    #pragma unroll
    for(int i=0;i<4;i++)
      #pragma unroll
      for(int u=0;u<4;u++)
        sS[(qb*4+i)*1032 + m0 + kb + 32*u] = acc[i][u]*SCALE1;
    if(kt<7){
      float* nbuf = sKV + ((kt+1)&1)*4608;
      #pragma unroll
      for(int r=0;r<4;r++) *(float4*)&nbuf[fm[r]*36 + fd[r]] = pf[r];
    }
    __syncthreads();
  }

  // prefetch V tile 0 (hidden under softmax)
  #pragma unroll
  for(int r=0;r<4;r++)
    pf[r] = *(const float4*)&g_kv1[kvbase + (size_t)fm[r]*256 + 128 + h*32 + fd[r]];

  // ---- softmax: warp w owns its own rows (written by same warp) ----
  {
    int w = t>>5, l = t&31;
    for(int qi=0;qi<4;qi++){
      float4* row4 = (float4*)(sS + (w*4+qi)*1032);
      float mx = -1e30f;
      #pragma unroll
      for(int i2=0;i2<8;i2++){
        float4 v = row4[l + 32*i2];
        mx = fmaxf(mx, fmaxf(fmaxf(v.x,v.y), fmaxf(v.z,v.w)));
      }
      mx = wredmax(mx);
      float sm = 0.f;
      #pragma unroll
      for(int i2=0;i2<8;i2++){
        float4 v = row4[l + 32*i2];
        v.x = __expf(v.x-mx); v.y = __expf(v.y-mx);
        v.z = __expf(v.z-mx); v.w = __expf(v.w-mx);
        row4[l+32*i2] = v;
        sm += (v.x+v.y)+(v.z+v.w);
      }
      sm = wredsum(sm);
      float inv = 1.f/sm;
      #pragma unroll
      for(int i2=0;i2<8;i2++){
        float4 v = row4[l+32*i2];
        v.x*=inv; v.y*=inv; v.z*=inv; v.w*=inv;
        row4[l+32*i2] = v;
      }
    }
  }
  // store V tile 0 into buf0 (scores done with sKV; softmax doesn't touch it)
  #pragma unroll
  for(int r=0;r<4;r++) *(float4*)&sKV[fm[r]*36 + fd[r]] = pf[r];
  __syncthreads();

  // ---- per-key partial sums for g (float4 over m) ----
  {
    float4 s4 = make_float4(0.f,0.f,0.f,0.f);
    #pragma unroll 8
    for(int q=0;q<32;q++){
      float4 v = *(const float4*)&sS[q*1032 + t*4];
      s4.x+=v.x; s4.y+=v.y; s4.z+=v.z; s4.w+=v.w;
    }
    *(float4*)&g_part[((size_t)(b*512 + h*128 + qt))*1024 + t*4] = s4;
  }

  // ---- AV: thread = (kq 8 x 16keys, qr 8 x 4q, dr 4 x 8dd), float4 loads ---
  int kq = t>>5;
  int qr = (t>>2)&7;
  int dr = t&3;
  float accv[4][8];
  #pragma unroll
  for(int i=0;i<4;i++)
    #pragma unroll
    for(int u=0;u<8;u++) accv[i][u] = 0.f;
  for(int kt=0;kt<8;kt++){
    float* buf = sKV + (kt&1)*4608;
    if(kt<7){
      #pragma unroll
      for(int r=0;r<4;r++)
        pf[r] = *(const float4*)&g_kv1[kvbase + (size_t)(((kt+1)<<7)+fm[r])*256 + 128 + h*32 + fd[r]];
    }
    int m0 = kt<<7;
    #pragma unroll
    for(int j4=0;j4<4;j4++){
      float4 p[4];
      #pragma unroll
      for(int i=0;i<4;i++)
        p[i] = *(const float4*)&sS[(qr*4+i)*1032 + m0 + kq*16 + j4*4];
      #pragma unroll
      for(int jj=0;jj<4;jj++){
        int mm = kq*16 + j4*4 + jj;
        float4 v0 = *(const float4*)&buf[mm*36 + dr*8];
        float4 v1 = *(const float4*)&buf[mm*36 + dr*8 + 4];
        float pv[4] = { ((const float*)&p[0])[jj], ((const float*)&p[1])[jj],
                        ((const float*)&p[2])[jj], ((const float*)&p[3])[jj] };
        #pragma unroll
        for(int i=0;i<4;i++){
          accv[i][0] = fmaf(pv[i], v0.x, accv[i][0]);
          accv[i][1] = fmaf(pv[i], v0.y, accv[i][1]);
          accv[i][2] = fmaf(pv[i], v0.z, accv[i][2]);
          accv[i][3] = fmaf(pv[i], v0.w, accv[i][3]);
          accv[i][4] = fmaf(pv[i], v1.x, accv[i][4]);
          accv[i][5] = fmaf(pv[i], v1.y, accv[i][5]);
          accv[i][6] = fmaf(pv[i], v1.z, accv[i][6]);
          accv[i][7] = fmaf(pv[i], v1.w, accv[i][7]);
        }
      }
    }
    if(kt<7){
      float* nbuf = sKV + ((kt+1)&1)*4608;
      #pragma unroll
      for(int r=0;r<4;r++) *(float4*)&nbuf[fm[r]*36 + fd[r]] = pf[r];
    }
    __syncthreads();
  }
  // reduce 8 key-group partials via sS scratch
  #pragma unroll
  for(int i=0;i<4;i++){
    float* dst = sS + kq*1024 + (qr*4+i)*32 + dr*8;
    *(float4*)&dst[0] = make_float4(accv[i][0],accv[i][1],accv[i][2],accv[i][3]);
    *(float4*)&dst[4] = make_float4(accv[i][4],accv[i][5],accv[i][6],accv[i][7]);
  }
  __syncthreads();
  {
    float4 s4 = make_float4(0.f,0.f,0.f,0.f);
    #pragma unroll
    for(int g=0; g<8; g++){
      float4 v = *(const float4*)&sS[g*1024 + t*4];
      s4.x+=v.x; s4.y+=v.y; s4.z+=v.z; s4.w+=v.w;
    }
    int oi = t*4;
    int q = oi>>5, dd = oi&31;
    *(float4*)&g_cat[((size_t)(b*4096+n0+q))*256 + h*32 + dd] = s4;
  }
}

// ---------------- g reduction (64 blocks, deterministic) ---------------------
__global__ void gred_k(){
  int b = blockIdx.x>>4;
  int ml = threadIdx.x&63;
  int pg = threadIdx.x>>6;
  int m = (blockIdx.x&15)*64 + ml;
  float s = 0.f;
  for(int p=pg; p<512; p+=4)
    s += g_part[((size_t)(b*512+p))*1024 + m];
  __shared__ float red[4][64];
  red[pg][ml] = s;
  __syncthreads();
  if(pg==0)
    g_gsum[b*1024+m] = (red[0][ml]+red[1][ml])+(red[2][ml]+red[3][ml]);
}

// ---------------- branch-2 window attention ----------------------------------
__global__ void attn2_k(){
  __shared__ float sQ[4][16][33], sK[4][16][33], sV[4][16][33];
  __shared__ float sS[4][16][17];
  int t = threadIdx.x;
  int win = blockIdx.x, b = blockIdx.y;
  int i1 = win>>4, j1 = win&15;
  for(int e=t;e<2048;e+=256){
    int h=e>>9, rem=e&511, tk=rem>>5, dd=rem&31;
    int n = ((i1*4 + (tk>>2))<<6) + j1*4 + (tk&3);
    size_t base = ((size_t)(b*4096+n))*768 + h*32+dd;
    sQ[h][tk][dd] = g_proj1[base+128];
    sK[h][tk][dd] = g_proj1[base+256];
    sV[h][tk][dd] = g_proj1[base+384];
  }
  __syncthreads();
  int h = t>>6, q = (t>>2)&15, kg = t&3;
  #pragma unroll
  for(int k2=0;k2<4;k2++){
    int kk = kg*4+k2;
    float s = 0.f;
    #pragma unroll
    for(int dd=0;dd<32;dd++) s = fmaf(sQ[h][q][dd], sK[h][kk][dd], s);
    sS[h][q][kk] = s*SCALE1;
  }
  __syncthreads();
  if(kg==0){
    float* row = sS[h][q];
    float mx=-1e30f;
    #pragma unroll
    for(int kk=0;kk<16;kk++) mx = fmaxf(mx,row[kk]);
    float sm=0.f;
    #pragma unroll
    for(int kk=0;kk<16;kk++){ float p=__expf(row[kk]-mx); row[kk]=p; sm+=p; }
    float inv=1.f/sm;
    #pragma unroll
    for(int kk=0;kk<16;kk++) row[kk]*=inv;
  }
  __syncthreads();
  float acc[8]={};
  int dd0 = kg*8;
  #pragma unroll
  for(int kk=0;kk<16;kk++){
    float p = sS[h][q][kk];
    #pragma unroll
    for(int u=0;u<8;u++) acc[u] = fmaf(p, sV[h][kk][dd0+u], acc[u]);
  }
  {
    int n = ((i1*4+(q>>2))<<6) + j1*4 + (q&3);
    float* dst = &g_cat[((size_t)(b*4096+n))*256 + 128 + h*32 + dd0];
    #pragma unroll
    for(int u=0;u<8;u++) dst[u] = acc[u];
  }
  if(t<16){
    float s=0.f;
    #pragma unroll
    for(int h2=0;h2<4;h2++)
      #pragma unroll
      for(int q2=0;q2<16;q2++) s += sS[h2][q2][t];
    int y = i1*4 + (t>>2), x = j1*4 + (t&3);
    g_lm[b*4096 + y*64 + x] = s*(1.f/64.f);
  }
}

// ---------------- depthwise lepe conv + concat add ---------------------------
__global__ void lepe_k(const float* __restrict__ lcb){
  int blk = blockIdx.x, c = threadIdx.x;
  int b = blk>>12, pos = blk&4095, y = pos>>6, x = pos&63;
  float acc = lcb[c];
  #pragma unroll
  for(int dy=-1;dy<=1;dy++){
    int yy = y+dy; if((unsigned)yy >= 64u) continue;
    #pragma unroll
    for(int dx=-1;dx<=1;dx++){
      int xx = x+dx; if((unsigned)xx >= 64u) continue;
      int tap = (dy+1)*3 + (dx+1);
      acc = fmaf(g_proj1[((size_t)(b*4096 + yy*64+xx))*768 + 512 + c],
                 g_lwT[tap*256+c], acc);
    }
  }
  size_t o = (size_t)blk*256 + c;
  g_pre[o] = g_cat[o] + acc;
}

// ---------------- mask assembly ----------------------------------------------
__global__ void mask_k(float* __restrict__ out){
  int idx = blockIdx.x*256 + threadIdx.x;      // 0..16383
  int b = idx>>12, pos = idx&4095, y = pos>>6, x = pos&63;
  float v = g_lm[idx] + g_gsum[b*1024 + (y>>1)*32 + (x>>1)] * (1.f/16384.f);
  out[4194304 + idx] = v;                       // mask1 [b, y*64+x]
  out[4210688 + b*4096 + x*64 + y] = v;         // mask2 [b, x*64+y]
}

// ---------------- launch -----------------------------------------------------
extern "C" void kernel_launch(void* const* d_in, const int* in_sizes, int n_in,
                              void* d_out, int out_size)
{
  const float* x    = (const float*)d_in[0];
  const float* q1w  = (const float*)d_in[1];
  const float* q1b  = (const float*)d_in[2];
  const float* kv1w = (const float*)d_in[3];
  const float* kv1b = (const float*)d_in[4];
  const float* q2w  = (const float*)d_in[5];
  const float* q2b  = (const float*)d_in[6];
  const float* kv2w = (const float*)d_in[7];
  const float* kv2b = (const float*)d_in[8];
  const float* lpw  = (const float*)d_in[9];
  const float* lpb  = (const float*)d_in[10];
  const float* lcw  = (const float*)d_in[11];
  const float* lcb  = (const float*)d_in[12];
  const float* srw  = (const float*)d_in[13];
  const float* srb  = (const float*)d_in[14];
  const float* nw   = (const float*)d_in[15];
  const float* nb   = (const float*)d_in[16];
  const float* pw   = (const float*)d_in[17];
  const float* pb   = (const float*)d_in[18];
  float* out = (float*)d_out;

  const int ATTN1_SMEM = (33024 + 1152 + 2*4608) * 4;  // 173568 B
  cudaFuncSetAttribute(attn1_k, cudaFuncAttributeMaxDynamicSharedMemorySize, ATTN1_SMEM);

  prep_k<<<256,256>>>(q1w,q2w,kv2w,lpw,q1b,q2b,kv2b,lpb,srw,lcw);
  gemm01_k<<<3328,256>>>(x, srb);                // proj1 + xs_pre fused
  attn2_k<<<dim3(256,4),256>>>();
  ln_gelu_k<<<4096,256>>>(nw, nb);
  gemm2_k<<<256,256>>>(kv1w, kv1b);              // kv1
  attn1_k<<<dim3(128,4,4), 256, ATTN1_SMEM>>>();
  gred_k<<<64,256>>>();
  lepe_k<<<16384,256>>>(lcb);
  gemm3_k<<<1024,256>>>(pw, pb, out);            // proj -> out
  mask_k<<<64,256>>>(out);
}

// round 11
// speedup vs baseline: 1.8583x; 1.0919x over previous
#include <cuda_runtime.h>
#include <math.h>

#define SCALE1 0.17677669529663687f  // 32^-0.5

// ---------------- scratch (static device globals; no allocation) ------------
__device__ float g_proj1[16384*768];   // [q1 | q2 | kv2(k,v) | lepe_lin]
__device__ float g_xs_pre[4096*256];
__device__ float g_xs[4096*256];
__device__ float g_kv1[4096*256];
__device__ float g_cat[16384*256];     // [x1 | x2]
__device__ float g_pre[16384*256];     // cat + lepe
__device__ float g_part[4*512*1024];   // per-(h,qtile) partial key-prob sums
__device__ float g_gsum[4*1024];
__device__ float g_lm[4*4096];
__device__ float g_Wcat[256*768];
__device__ float g_bcat[768];
__device__ float g_srwT[1024*256];     // (seg*256+ic, oc)
__device__ float g_lwT[9*256];         // (tap, c)

// ---------------- helpers ---------------------------------------------------
__device__ __forceinline__ float wredmax(float v){
  #pragma unroll
  for(int o=16;o;o>>=1) v = fmaxf(v, __shfl_xor_sync(0xFFFFFFFFu, v, o));
  return v;
}
__device__ __forceinline__ float wredsum(float v){
  #pragma unroll
  for(int o=16;o;o>>=1) v += __shfl_xor_sync(0xFFFFFFFFu, v, o);
  return v;
}

__global__ void nop_k(){}

// ---------------- weight prep ------------------------------------------------
__global__ void prep_k(const float* __restrict__ q1w, const float* __restrict__ q2w,
                       const float* __restrict__ kv2w, const float* __restrict__ lpw,
                       const float* __restrict__ q1b, const float* __restrict__ q2b,
                       const float* __restrict__ kv2b, const float* __restrict__ lpb,
                       const float* __restrict__ srw, const float* __restrict__ lcw)
{
  int i0 = blockIdx.x*blockDim.x + threadIdx.x;
  int st = gridDim.x*blockDim.x;
  for(int idx=i0; idx<256*768; idx+=st){
    int k = idx/768, c = idx%768;
    float v;
    if(c<128)      v = q1w[k*128+c];
    else if(c<256) v = q2w[k*128+c-128];
    else if(c<512) v = kv2w[k*256+c-256];
    else           v = lpw[k*256+c-512];
    g_Wcat[idx] = v;
  }
  for(int c=i0;c<768;c+=st)
    g_bcat[c] = (c<128)?q1b[c]:(c<256)?q2b[c-128]:(c<512)?kv2b[c-256]:lpb[c-512];
  for(int idx=i0; idx<1024*256; idx+=st){
    int k = idx>>8, oc = idx&255;
    int seg = k>>8, ic = k&255;
    g_srwT[idx] = srw[(oc*256+ic)*4 + seg];
  }
  for(int idx=i0; idx<9*256; idx+=st){
    int tap = idx>>8, c = idx&255;
    g_lwT[idx] = lcw[c*9+tap];
  }
}

// ---------------- 128x128 GEMM body, 256 thr, 8x8 micro (scalar) ------------
// MODE 0: x(16384x256) @ g_Wcat(256x768)+g_bcat -> g_proj1
// MODE 3: g_pre(16384x256) @ proj_w(256x256)+proj_b, x2 -> d_out
template<int MODE>
__device__ __forceinline__ void gemm_big(const float* __restrict__ A,
                                         const float* __restrict__ B,
                                         const float* __restrict__ bi,
                                         float* __restrict__ C,
                                         int by, int bx)
{
  constexpr int K  = 256;
  constexpr int Nn = (MODE==0)?768:256;
  __shared__ float sA[16][136];
  __shared__ float sB[16][136];
  int t = threadIdx.x;
  int row0 = by*128, col0 = bx*128;
  int lr = t>>1;            // A row 0..127
  int lk = (t&1)*8;         // A k-offset
  int bk = t>>4;            // B k-row
  int bn = (t&15)*8;        // B col offset
  int tr = (t>>4)*4, tc = (t&15)*4;   // micro-tile: rows {tr+i, 64+tr+i}, cols {tc+j, 64+tc+j}
  float acc[2][4][2][4];
  #pragma unroll
  for(int a=0;a<2;a++)
    #pragma unroll
    for(int i=0;i<4;i++)
      #pragma unroll
      for(int b2=0;b2<2;b2++)
        #pragma unroll
        for(int j=0;j<4;j++) acc[a][i][b2][j] = 0.f;

  for(int kt=0; kt<16; kt++){
    int k0 = kt*16;
    const float* ap = A + (size_t)(row0+lr)*K + k0 + lk;
    float4 a0 = *(const float4*)ap;
    float4 a1 = *(const float4*)(ap+4);
    const float* bp = B + (size_t)(k0+bk)*Nn + col0 + bn;
    float4 b0 = *(const float4*)bp;
    float4 b1 = *(const float4*)(bp+4);
    __syncthreads();
    sA[lk+0][lr]=a0.x; sA[lk+1][lr]=a0.y; sA[lk+2][lr]=a0.z; sA[lk+3][lr]=a0.w;
    sA[lk+4][lr]=a1.x; sA[lk+5][lr]=a1.y; sA[lk+6][lr]=a1.z; sA[lk+7][lr]=a1.w;
    *(float4*)&sB[bk][bn]   = b0;
    *(float4*)&sB[bk][bn+4] = b1;
    __syncthreads();
    #pragma unroll
    for(int kk=0;kk<16;kk++){
      float4 av0 = *(const float4*)&sA[kk][tr];
      float4 av1 = *(const float4*)&sA[kk][64+tr];
      float4 bv0 = *(const float4*)&sB[kk][tc];
      float4 bv1 = *(const float4*)&sB[kk][64+tc];
      float ar[2][4] = {{av0.x,av0.y,av0.z,av0.w},{av1.x,av1.y,av1.z,av1.w}};
      float br[2][4] = {{bv0.x,bv0.y,bv0.z,bv0.w},{bv1.x,bv1.y,bv1.z,bv1.w}};
      #pragma unroll
      for(int a=0;a<2;a++)
        #pragma unroll
        for(int i=0;i<4;i++)
          #pragma unroll
          for(int b2=0;b2<2;b2++)
            #pragma unroll
            for(int j=0;j<4;j++)
              acc[a][i][b2][j] = fmaf(ar[a][i], br[b2][j], acc[a][i][b2][j]);
    }
  }
  #pragma unroll
  for(int a=0;a<2;a++)
    #pragma unroll
    for(int i=0;i<4;i++){
      int r = row0 + a*64 + tr + i;
      #pragma unroll
      for(int b2=0;b2<2;b2++){
        int c = col0 + b2*64 + tc;
        float4 v4;
        v4.x = acc[a][i][b2][0]+bi[c+0];
        v4.y = acc[a][i][b2][1]+bi[c+1];
        v4.z = acc[a][i][b2][2]+bi[c+2];
        v4.w = acc[a][i][b2][3]+bi[c+3];
        if(MODE==3){ v4.x*=2.f; v4.y*=2.f; v4.z*=2.f; v4.w*=2.f; }
        *(float4*)&C[(size_t)r*Nn + c] = v4;
      }
    }
}

// ---------------- 64x64 tiled GEMM body, 256 thr, 4x4 micro ------------------
// MODE 1: gather-x(4096x1024) @ g_srwT(1024x256)+sr_b -> g_xs_pre
// MODE 2: g_xs(4096x256) @ kv1_w(256x256)+kv1_b -> g_kv1
template<int MODE>
__device__ __forceinline__ void gemm_body(const float* __restrict__ A,
                                          const float* __restrict__ B,
                                          const float* __restrict__ bi,
                                          float* __restrict__ C,
                                          int by, int bx)
{
  constexpr int K  = (MODE==1)?1024:256;
  constexpr int Nn = 256;
  __shared__ float sA[16][68];
  __shared__ float sB[16][68];
  int t = threadIdx.x;
  int row0 = by*64, col0 = bx*64;
  int la_m = t>>2, la_k = (t&3)<<2;
  int lb_k = t>>4, lb_n = (t&15)<<2;
  int tr = (t>>4)<<2, tc = (t&15)<<2;
  float acc[4][4] = {};
  for(int kt=0; kt<(K>>4); kt++){
    float4 a4;
    if(MODE==1){
      int r = row0+la_m;
      int b = r>>10, p = r&1023, i = p>>5, j = p&31;
      int k = (kt<<4)+la_k;
      int seg = k>>8, ic = k&255;
      int tok = ((2*i + (seg>>1))<<6) + 2*j + (seg&1);
      a4 = *(const float4*)(A + (size_t)((b<<12)+tok)*256 + ic);
    } else {
      a4 = *(const float4*)(A + (size_t)(row0+la_m)*K + (kt<<4)+la_k);
    }
    float4 b4 = *(const float4*)(B + (size_t)((kt<<4)+lb_k)*Nn + col0+lb_n);
    __syncthreads();
    sA[la_k][la_m]=a4.x; sA[la_k+1][la_m]=a4.y;
    sA[la_k+2][la_m]=a4.z; sA[la_k+3][la_m]=a4.w;
    *(float4*)&sB[lb_k][lb_n] = b4;
    __syncthreads();
    #pragma unroll
    for(int kk=0;kk<16;kk++){
      float4 av=*(const float4*)&sA[kk][tr];
      float4 bv=*(const float4*)&sB[kk][tc];
      float ar[4]={av.x,av.y,av.z,av.w}, br[4]={bv.x,bv.y,bv.z,bv.w};
      #pragma unroll
      for(int i=0;i<4;i++)
        #pragma unroll
        for(int j=0;j<4;j++) acc[i][j] = fmaf(ar[i],br[j],acc[i][j]);
    }
  }
  #pragma unroll
  for(int i=0;i<4;i++){
    int r = row0+tr+i;
    float4 v4;
    v4.x = acc[i][0]+bi[col0+tc+0];
    v4.y = acc[i][1]+bi[col0+tc+1];
    v4.z = acc[i][2]+bi[col0+tc+2];
    v4.w = acc[i][3]+bi[col0+tc+3];
    *(float4*)&C[(size_t)r*Nn + col0+tc] = v4;
  }
}

// fused: blocks [0,768) = mode0 big (128x6 tiles), [768,1024) = mode1 (64x4)
__global__ void gemm01_k(const float* __restrict__ x, const float* __restrict__ srb){
  int bid = blockIdx.x;
  if(bid < 768) gemm_big<0>(x, g_Wcat, g_bcat, g_proj1, bid/6, bid%6);
  else { int b2 = bid-768; gemm_body<1>(x, g_srwT, srb, g_xs_pre, b2>>2, b2&3); }
}
__global__ void gemm2_k(const float* __restrict__ kv1w, const float* __restrict__ kv1b){
  gemm_body<2>(g_xs, kv1w, kv1b, g_kv1, blockIdx.x>>2, blockIdx.x&3);
}
__global__ void gemm3_k(const float* __restrict__ pw, const float* __restrict__ pb,
                        float* __restrict__ out){
  gemm_big<3>(g_pre, pw, pb, out, blockIdx.x>>1, blockIdx.x&1);
}

// ---------------- LayerNorm + exact GELU ------------------------------------
__global__ void ln_gelu_k(const float* __restrict__ nw, const float* __restrict__ nb){
  int r = blockIdx.x, c = threadIdx.x;
  float v = g_xs_pre[(size_t)r*256+c];
  float s = v, s2 = v*v;
  #pragma unroll
  for(int o=16;o;o>>=1){ s += __shfl_xor_sync(~0u,s,o); s2 += __shfl_xor_sync(~0u,s2,o); }
  __shared__ float rs[8], rs2[8];
  int w = c>>5, l = c&31;
  if(l==0){ rs[w]=s; rs2[w]=s2; }
  __syncthreads();
  if(w==0){
    float a=(l<8)?rs[l]:0.f, a2=(l<8)?rs2[l]:0.f;
    #pragma unroll
    for(int o=4;o;o>>=1){ a+=__shfl_xor_sync(~0u,a,o); a2+=__shfl_xor_sync(~0u,a2,o); }
    if(l==0){ rs[0]=a; rs2[0]=a2; }
  }
  __syncthreads();
  float m  = rs[0]*(1.f/256.f);
  float var= rs2[0]*(1.f/256.f) - m*m;
  float y  = (v-m)*rsqrtf(var+1e-5f)*nw[c] + nb[c];
  g_xs[(size_t)r*256+c] = 0.5f*y*(1.f+erff(y*0.70710678118f));
}

// ---------------- branch-1 attention (R9-proven) -----------------------------
// grid (128 qtiles, 4 heads, 4 batch), 256 threads
extern __shared__ float dsm[];
__global__ void attn1_k(){
  float* sS  = dsm;               // 33024 floats
  float* sQ  = sS + 33024;        // 1152
  float* sKV = sQ + 1152;         // 2 * 4608
  int t = threadIdx.x;
  int qt = blockIdx.x, h = blockIdx.y, b = blockIdx.z;
  int n0 = qt*32;
  int fm[4], fd[4];
  #pragma unroll
  for(int r=0;r<4;r++){ int e = t + 256*r; fm[r] = e>>3; fd[r] = (e&7)<<2; }
  size_t kvbase = (size_t)(b<<10)*256;

  {
    int q = t>>3, d4 = (t&7)<<2;
    *(float4*)&sQ[q*36+d4] =
      *(const float4*)&g_proj1[((size_t)(b*4096+n0+q))*768 + h*32 + d4];
  }
  float4 pf[4];
  #pragma unroll
  for(int r=0;r<4;r++)
    pf[r] = *(const float4*)&g_kv1[kvbase + (size_t)fm[r]*256 + h*32 + fd[r]];
  __syncthreads();
  #pragma unroll
  for(int r=0;r<4;r++) *(float4*)&sKV[fm[r]*36 + fd[r]] = pf[r];
  __syncthreads();

  // ---- scores ----
  int qb = t>>5, kb = t&31;
  for(int kt=0;kt<8;kt++){
    float* buf = sKV + (kt&1)*4608;
    if(kt<7){
      #pragma unroll
      for(int r=0;r<4;r++)
        pf[r] = *(const float4*)&g_kv1[kvbase + (size_t)(((kt+1)<<7)+fm[r])*256 + h*32 + fd[r]];
    }
    float acc[4][4] = {};
    #pragma unroll
    for(int d4=0; d4<8; d4++){
      float4 qv[4], kv[4];
      #pragma unroll
      for(int i=0;i<4;i++) qv[i] = *(const float4*)&sQ[(qb*4+i)*36 + (d4<<2)];
      #pragma unroll
      for(int u=0;u<4;u++) kv[u] = *(const float4*)&buf[(kb+32*u)*36 + (d4<<2)];
      #pragma unroll
      for(int i=0;i<4;i++)
        #pragma unroll
        for(int u=0;u<4;u++){
          acc[i][u] = fmaf(qv[i].x, kv[u].x, acc[i][u]);
          acc[i][u] = fmaf(qv[i].y, kv[u].y, acc[i][u]);
          acc[i][u] = fmaf(qv[i].z, kv[u].z, acc[i][u]);
          acc[i][u] = fmaf(qv[i].w, kv[u].w, acc[i][u]);
        }
    }
    int m0 = kt<<7;
    #pragma unroll
    for(int i=0;i<4;i++)
      #pragma unroll
      for(int u=0;u<4;u++)
        sS[(qb*4+i)*1032 + m0 + kb + 32*u] = acc[i][u]*SCALE1;
    if(kt<7){
      float* nbuf = sKV + ((kt+1)&1)*4608;
      #pragma unroll
      for(int r=0;r<4;r++) *(float4*)&nbuf[fm[r]*36 + fd[r]] = pf[r];
    }
    __syncthreads();
  }

  // prefetch V tile 0 (hidden under softmax)
  #pragma unroll
  for(int r=0;r<4;r++)
    pf[r] = *(const float4*)&g_kv1[kvbase + (size_t)fm[r]*256 + 128 + h*32 + fd[r]];

  // ---- softmax ----
  {
    int w = t>>5, l = t&31;
    for(int qi=0;qi<4;qi++){
      float4* row4 = (float4*)(sS + (w*4+qi)*1032);
      float mx = -1e30f;
      #pragma unroll
      for(int i2=0;i2<8;i2++){
        float4 v = row4[l + 32*i2];
        mx = fmaxf(mx, fmaxf(fmaxf(v.x,v.y), fmaxf(v.z,v.w)));
      }
      mx = wredmax(mx);
      float sm = 0.f;
      #pragma unroll
      for(int i2=0;i2<8;i2++){
        float4 v = row4[l + 32*i2];
        v.x = __expf(v.x-mx); v.y = __expf(v.y-mx);
        v.z = __expf(v.z-mx); v.w = __expf(v.w-mx);
        row4[l+32*i2] = v;
        sm += (v.x+v.y)+(v.z+v.w);
      }
      sm = wredsum(sm);
      float inv = 1.f/sm;
      #pragma unroll
      for(int i2=0;i2<8;i2++){
        float4 v = row4[l+32*i2];
        v.x*=inv; v.y*=inv; v.z*=inv; v.w*=inv;
        row4[l+32*i2] = v;
      }
    }
  }
  #pragma unroll
  for(int r=0;r<4;r++) *(float4*)&sKV[fm[r]*36 + fd[r]] = pf[r];
  __syncthreads();

  // ---- per-key partial sums for g ----
  {
    float4 s4 = make_float4(0.f,0.f,0.f,0.f);
    #pragma unroll 8
    for(int q=0;q<32;q++){
      float4 v = *(const float4*)&sS[q*1032 + t*4];
      s4.x+=v.x; s4.y+=v.y; s4.z+=v.z; s4.w+=v.w;
    }
    *(float4*)&g_part[((size_t)(b*512 + h*128 + qt))*1024 + t*4] = s4;
  }

  // ---- AV ----
  int kq = t>>5;
  int qr = (t>>2)&7;
  int dr = t&3;
  float accv[4][8];
  #pragma unroll
  for(int i=0;i<4;i++)
    #pragma unroll
    for(int u=0;u<8;u++) accv[i][u] = 0.f;
  for(int kt=0;kt<8;kt++){
    float* buf = sKV + (kt&1)*4608;
    if(kt<7){
      #pragma unroll
      for(int r=0;r<4;r++)
        pf[r] = *(const float4*)&g_kv1[kvbase + (size_t)(((kt+1)<<7)+fm[r])*256 + 128 + h*32 + fd[r]];
    }
    int m0 = kt<<7;
    #pragma unroll
    for(int j4=0;j4<4;j4++){
      float4 p[4];
      #pragma unroll
      for(int i=0;i<4;i++)
        p[i] = *(const float4*)&sS[(qr*4+i)*1032 + m0 + kq*16 + j4*4];
      #pragma unroll
      for(int jj=0;jj<4;jj++){
        int mm = kq*16 + j4*4 + jj;
        float4 v0 = *(const float4*)&buf[mm*36 + dr*8];
        float4 v1 = *(const float4*)&buf[mm*36 + dr*8 + 4];
        float pv[4] = { ((const float*)&p[0])[jj], ((const float*)&p[1])[jj],
                        ((const float*)&p[2])[jj], ((const float*)&p[3])[jj] };
        #pragma unroll
        for(int i=0;i<4;i++){
          accv[i][0] = fmaf(pv[i], v0.x, accv[i][0]);
          accv[i][1] = fmaf(pv[i], v0.y, accv[i][1]);
          accv[i][2] = fmaf(pv[i], v0.z, accv[i][2]);
          accv[i][3] = fmaf(pv[i], v0.w, accv[i][3]);
          accv[i][4] = fmaf(pv[i], v1.x, accv[i][4]);
          accv[i][5] = fmaf(pv[i], v1.y, accv[i][5]);
          accv[i][6] = fmaf(pv[i], v1.z, accv[i][6]);
          accv[i][7] = fmaf(pv[i], v1.w, accv[i][7]);
        }
      }
    }
    if(kt<7){
      float* nbuf = sKV + ((kt+1)&1)*4608;
      #pragma unroll
      for(int r=0;r<4;r++) *(float4*)&nbuf[fm[r]*36 + fd[r]] = pf[r];
    }
    __syncthreads();
  }
  #pragma unroll
  for(int i=0;i<4;i++){
    float* dst = sS + kq*1024 + (qr*4+i)*32 + dr*8;
    *(float4*)&dst[0] = make_float4(accv[i][0],accv[i][1],accv[i][2],accv[i][3]);
    *(float4*)&dst[4] = make_float4(accv[i][4],accv[i][5],accv[i][6],accv[i][7]);
  }
  __syncthreads();
  {
    float4 s4 = make_float4(0.f,0.f,0.f,0.f);
    #pragma unroll
    for(int g=0; g<8; g++){
      float4 v = *(const float4*)&sS[g*1024 + t*4];
      s4.x+=v.x; s4.y+=v.y; s4.z+=v.z; s4.w+=v.w;
    }
    int oi = t*4;
    int q = oi>>5, dd = oi&31;
    *(float4*)&g_cat[((size_t)(b*4096+n0+q))*256 + h*32 + dd] = s4;
  }
}

// ---------------- g reduction (64 blocks, deterministic) ---------------------
__global__ void gred_k(){
  int b = blockIdx.x>>4;
  int ml = threadIdx.x&63;
  int pg = threadIdx.x>>6;
  int m = (blockIdx.x&15)*64 + ml;
  float s = 0.f;
  for(int p=pg; p<512; p+=4)
    s += g_part[((size_t)(b*512+p))*1024 + m];
  __shared__ float red[4][64];
  red[pg][ml] = s;
  __syncthreads();
  if(pg==0)
    g_gsum[b*1024+m] = (red[0][ml]+red[1][ml])+(red[2][ml]+red[3][ml]);
}

// ---------------- branch-2 window attention ----------------------------------
__global__ void attn2_k(){
  __shared__ float sQ[4][16][33], sK[4][16][33], sV[4][16][33];
  __shared__ float sS[4][16][17];
  int t = threadIdx.x;
  int win = blockIdx.x, b = blockIdx.y;
  int i1 = win>>4, j1 = win&15;
  for(int e=t;e<2048;e+=256){
    int h=e>>9, rem=e&511, tk=rem>>5, dd=rem&31;
    int n = ((i1*4 + (tk>>2))<<6) + j1*4 + (tk&3);
    size_t base = ((size_t)(b*4096+n))*768 + h*32+dd;
    sQ[h][tk][dd] = g_proj1[base+128];
    sK[h][tk][dd] = g_proj1[base+256];
    sV[h][tk][dd] = g_proj1[base+384];
  }
  __syncthreads();
  int h = t>>6, q = (t>>2)&15, kg = t&3;
  #pragma unroll
  for(int k2=0;k2<4;k2++){
    int kk = kg*4+k2;
    float s = 0.f;
    #pragma unroll
    for(int dd=0;dd<32;dd++) s = fmaf(sQ[h][q][dd], sK[h][kk][dd], s);
    sS[h][q][kk] = s*SCALE1;
  }
  __syncthreads();
  if(kg==0){
    float* row = sS[h][q];
    float mx=-1e30f;
    #pragma unroll
    for(int kk=0;kk<16;kk++) mx = fmaxf(mx,row[kk]);
    float sm=0.f;
    #pragma unroll
    for(int kk=0;kk<16;kk++){ float p=__expf(row[kk]-mx); row[kk]=p; sm+=p; }
    float inv=1.f/sm;
    #pragma unroll
    for(int kk=0;kk<16;kk++) row[kk]*=inv;
  }
  __syncthreads();
  float acc[8]={};
  int dd0 = kg*8;
  #pragma unroll
  for(int kk=0;kk<16;kk++){
    float p = sS[h][q][kk];
    #pragma unroll
    for(int u=0;u<8;u++) acc[u] = fmaf(p, sV[h][kk][dd0+u], acc[u]);
  }
  {
    int n = ((i1*4+(q>>2))<<6) + j1*4 + (q&3);
    float* dst = &g_cat[((size_t)(b*4096+n))*256 + 128 + h*32 + dd0];
    #pragma unroll
    for(int u=0;u<8;u++) dst[u] = acc[u];
  }
  if(t<16){
    float s=0.f;
    #pragma unroll
    for(int h2=0;h2<4;h2++)
      #pragma unroll
      for(int q2=0;q2<16;q2++) s += sS[h2][q2][t];
    int y = i1*4 + (t>>2), x = j1*4 + (t&3);
    g_lm[b*4096 + y*64 + x] = s*(1.f/64.f);
  }
}

// ---------------- depthwise lepe conv + concat add ---------------------------
__global__ void lepe_k(const float* __restrict__ lcb){
  int blk = blockIdx.x, c = threadIdx.x;
  int b = blk>>12, pos = blk&4095, y = pos>>6, x = pos&63;
  float acc = lcb[c];
  #pragma unroll
  for(int dy=-1;dy<=1;dy++){
    int yy = y+dy; if((unsigned)yy >= 64u) continue;
    #pragma unroll
    for(int dx=-1;dx<=1;dx++){
      int xx = x+dx; if((unsigned)xx >= 64u) continue;
      int tap = (dy+1)*3 + (dx+1);
      acc = fmaf(g_proj1[((size_t)(b*4096 + yy*64+xx))*768 + 512 + c],
                 g_lwT[tap*256+c], acc);
    }
  }
  size_t o = (size_t)blk*256 + c;
  g_pre[o] = g_cat[o] + acc;
}

// ---------------- mask assembly ----------------------------------------------
__global__ void mask_k(float* __restrict__ out){
  int idx = blockIdx.x*256 + threadIdx.x;      // 0..16383
  int b = idx>>12, pos = idx&4095, y = pos>>6, x = pos&63;
  float v = g_lm[idx] + g_gsum[b*1024 + (y>>1)*32 + (x>>1)] * (1.f/16384.f);
  out[4194304 + idx] = v;                       // mask1 [b, y*64+x]
  out[4210688 + b*4096 + x*64 + y] = v;         // mask2 [b, x*64+y]
}

// ---------------- launch -----------------------------------------------------
extern "C" void kernel_launch(void* const* d_in, const int* in_sizes, int n_in,
                              void* d_out, int out_size)
{
  const float* x    = (const float*)d_in[0];
  const float* q1w  = (const float*)d_in[1];
  const float* q1b  = (const float*)d_in[2];
  const float* kv1w = (const float*)d_in[3];
  const float* kv1b = (const float*)d_in[4];
  const float* q2w  = (const float*)d_in[5];
  const float* q2b  = (const float*)d_in[6];
  const float* kv2w = (const float*)d_in[7];
  const float* kv2b = (const float*)d_in[8];
  const float* lpw  = (const float*)d_in[9];
  const float* lpb  = (const float*)d_in[10];
  const float* lcw  = (const float*)d_in[11];
  const float* lcb  = (const float*)d_in[12];
  const float* srw  = (const float*)d_in[13];
  const float* srb  = (const float*)d_in[14];
  const float* nw   = (const float*)d_in[15];
  const float* nb   = (const float*)d_in[16];
  const float* pw   = (const float*)d_in[17];
  const float* pb   = (const float*)d_in[18];
  float* out = (float*)d_out;

  const int ATTN1_SMEM = (33024 + 1152 + 2*4608) * 4;  // 173568 B
  cudaFuncSetAttribute(attn1_k, cudaFuncAttributeMaxDynamicSharedMemorySize, ATTN1_SMEM);

  prep_k<<<256,256>>>(q1w,q2w,kv2w,lpw,q1b,q2b,kv2b,lpb,srw,lcw);
  nop_k<<<1,32>>>();
  nop_k<<<1,32>>>();
  gemm01_k<<<1024,256>>>(x, srb);                // proj1(big) + xs_pre fused; profiled slot
  attn2_k<<<dim3(256,4),256>>>();
  ln_gelu_k<<<4096,256>>>(nw, nb);
  gemm2_k<<<256,256>>>(kv1w, kv1b);              // kv1
  attn1_k<<<dim3(128,4,4), 256, ATTN1_SMEM>>>();
  gred_k<<<64,256>>>();
  lepe_k<<<16384,256>>>(lcb);
  gemm3_k<<<256,256>>>(pw, pb, out);             // proj(big) -> out
  mask_k<<<64,256>>>(out);
}

// round 12
// speedup vs baseline: 1.8962x; 1.0204x over previous
#include <cuda_runtime.h>
#include <math.h>

#define SCALE1 0.17677669529663687f  // 32^-0.5

typedef unsigned long long u64;

// ---------------- f32x2 packed helpers --------------------------------------
__device__ __forceinline__ u64 ffma2(u64 a, u64 b, u64 c){
  u64 d; asm("fma.rn.f32x2 %0, %1, %2, %3;" : "=l"(d) : "l"(a), "l"(b), "l"(c));
  return d;
}
__device__ __forceinline__ u64 pk2(float x, float y){
  u64 r; asm("mov.b64 %0, {%1, %2};" : "=l"(r) : "f"(x), "f"(y));
  return r;
}
__device__ __forceinline__ float2 up2(u64 v){
  float2 f; asm("mov.b64 {%0, %1}, %2;" : "=f"(f.x), "=f"(f.y) : "l"(v));
  return f;
}

// ---------------- scratch (static device globals; no allocation) ------------
__device__ float g_proj1[16384*768];   // [q1 | q2 | kv2(k,v) | lepe_lin]
__device__ float g_xs_pre[4096*256];
__device__ float g_xs[4096*256];
__device__ float g_kv1[4096*256];
__device__ float g_cat[16384*256];     // [x1 | x2]
__device__ float g_pre[16384*256];     // cat + lepe
__device__ float g_part[4*512*1024];   // per-(h,qtile) partial key-prob sums
__device__ float g_gsum[4*1024];
__device__ float g_lm[4*4096];
__device__ float g_Wcat[256*768];
__device__ float g_bcat[768];
__device__ float g_srwT[1024*256];     // (seg*256+ic, oc)
__device__ float g_lwT[9*256];         // (tap, c)

// ---------------- helpers ---------------------------------------------------
__device__ __forceinline__ float wredmax(float v){
  #pragma unroll
  for(int o=16;o;o>>=1) v = fmaxf(v, __shfl_xor_sync(0xFFFFFFFFu, v, o));
  return v;
}
__device__ __forceinline__ float wredsum(float v){
  #pragma unroll
  for(int o=16;o;o>>=1) v += __shfl_xor_sync(0xFFFFFFFFu, v, o);
  return v;
}

__global__ void nop_k(){}

// ---------------- weight prep ------------------------------------------------
__global__ void prep_k(const float* __restrict__ q1w, const float* __restrict__ q2w,
                       const float* __restrict__ kv2w, const float* __restrict__ lpw,
                       const float* __restrict__ q1b, const float* __restrict__ q2b,
                       const float* __restrict__ kv2b, const float* __restrict__ lpb,
                       const float* __restrict__ srw, const float* __restrict__ lcw)
{
  int i0 = blockIdx.x*blockDim.x + threadIdx.x;
  int st = gridDim.x*blockDim.x;
  for(int idx=i0; idx<256*768; idx+=st){
    int k = idx/768, c = idx%768;
    float v;
    if(c<128)      v = q1w[k*128+c];
    else if(c<256) v = q2w[k*128+c-128];
    else if(c<512) v = kv2w[k*256+c-256];
    else           v = lpw[k*256+c-512];
    g_Wcat[idx] = v;
  }
  for(int c=i0;c<768;c+=st)
    g_bcat[c] = (c<128)?q1b[c]:(c<256)?q2b[c-128]:(c<512)?kv2b[c-256]:lpb[c-512];
  for(int idx=i0; idx<1024*256; idx+=st){
    int k = idx>>8, oc = idx&255;
    int seg = k>>8, ic = k&255;
    g_srwT[idx] = srw[(oc*256+ic)*4 + seg];
  }
  for(int idx=i0; idx<9*256; idx+=st){
    int tap = idx>>8, c = idx&255;
    g_lwT[idx] = lcw[c*9+tap];
  }
}

// ---------------- 128x128 GEMM body, 256 thr, 8x8 micro, FFMA2 --------------
// MODE 0: x(16384x256) @ g_Wcat(256x768)+g_bcat -> g_proj1
// MODE 3: g_pre(16384x256) @ proj_w(256x256)+proj_b, x2 -> d_out
template<int MODE>
__device__ __forceinline__ void gemm_big(const float* __restrict__ A,
                                         const float* __restrict__ B,
                                         const float* __restrict__ bi,
                                         float* __restrict__ C,
                                         int by, int bx)
{
  constexpr int K  = 256;
  constexpr int Nn = (MODE==0)?768:256;
  __shared__ __align__(16) float sA[16][136];
  __shared__ __align__(16) float sB[16][136];
  int t = threadIdx.x;
  int row0 = by*128, col0 = bx*128;
  int lr = t>>1;            // A row 0..127
  int lk = (t&1)*8;         // A k-offset
  int bk = t>>4;            // B k-row
  int bn = (t&15)*8;        // B col offset
  int tr = (t>>4)*4, tc = (t&15)*4;   // micro: rows {tr+i, 64+tr+i}, cols {tc.., 64+tc..}
  // acc[a][i][j]: row = a*64+tr+i, colpair j: j<2 -> cols tc+2j..  j>=2 -> 64+tc+2(j-2)..
  u64 acc[2][4][4];
  #pragma unroll
  for(int a=0;a<2;a++)
    #pragma unroll
    for(int i=0;i<4;i++)
      #pragma unroll
      for(int j=0;j<4;j++) acc[a][i][j] = 0ull;

  for(int kt=0; kt<16; kt++){
    int k0 = kt*16;
    const float* ap = A + (size_t)(row0+lr)*K + k0 + lk;
    float4 a0 = *(const float4*)ap;
    float4 a1 = *(const float4*)(ap+4);
    const float* bp = B + (size_t)(k0+bk)*Nn + col0 + bn;
    float4 b0 = *(const float4*)bp;
    float4 b1 = *(const float4*)(bp+4);
    __syncthreads();
    sA[lk+0][lr]=a0.x; sA[lk+1][lr]=a0.y; sA[lk+2][lr]=a0.z; sA[lk+3][lr]=a0.w;
    sA[lk+4][lr]=a1.x; sA[lk+5][lr]=a1.y; sA[lk+6][lr]=a1.z; sA[lk+7][lr]=a1.w;
    *(float4*)&sB[bk][bn]   = b0;
    *(float4*)&sB[bk][bn+4] = b1;
    __syncthreads();
    #pragma unroll
    for(int kk=0;kk<16;kk++){
      float4 av0 = *(const float4*)&sA[kk][tr];
      float4 av1 = *(const float4*)&sA[kk][64+tr];
      ulonglong2 bb0 = *(const ulonglong2*)&sB[kk][tc];
      ulonglong2 bb1 = *(const ulonglong2*)&sB[kk][64+tc];
      u64 bp4[4] = {bb0.x, bb0.y, bb1.x, bb1.y};
      float ar[2][4] = {{av0.x,av0.y,av0.z,av0.w},{av1.x,av1.y,av1.z,av1.w}};
      #pragma unroll
      for(int a=0;a<2;a++)
        #pragma unroll
        for(int i=0;i<4;i++){
          u64 ad = pk2(ar[a][i], ar[a][i]);
          #pragma unroll
          for(int j=0;j<4;j++)
            acc[a][i][j] = ffma2(ad, bp4[j], acc[a][i][j]);
        }
    }
  }
  #pragma unroll
  for(int a=0;a<2;a++)
    #pragma unroll
    for(int i=0;i<4;i++){
      int r = row0 + a*64 + tr + i;
      #pragma unroll
      for(int b2=0;b2<2;b2++){
        int c = col0 + b2*64 + tc;
        float2 p0 = up2(acc[a][i][b2*2+0]);
        float2 p1 = up2(acc[a][i][b2*2+1]);
        float4 v4;
        v4.x = p0.x+bi[c+0];
        v4.y = p0.y+bi[c+1];
        v4.z = p1.x+bi[c+2];
        v4.w = p1.y+bi[c+3];
        if(MODE==3){ v4.x*=2.f; v4.y*=2.f; v4.z*=2.f; v4.w*=2.f; }
        *(float4*)&C[(size_t)r*Nn + c] = v4;
      }
    }
}

// ---------------- 64x64 tiled GEMM body, 256 thr, 4x4 micro ------------------
// MODE 1: gather-x(4096x1024) @ g_srwT(1024x256)+sr_b -> g_xs_pre
// MODE 2: g_xs(4096x256) @ kv1_w(256x256)+kv1_b -> g_kv1
template<int MODE>
__device__ __forceinline__ void gemm_body(const float* __restrict__ A,
                                          const float* __restrict__ B,
                                          const float* __restrict__ bi,
                                          float* __restrict__ C,
                                          int by, int bx)
{
  constexpr int K  = (MODE==1)?1024:256;
  constexpr int Nn = 256;
  __shared__ float sA[16][68];
  __shared__ float sB[16][68];
  int t = threadIdx.x;
  int row0 = by*64, col0 = bx*64;
  int la_m = t>>2, la_k = (t&3)<<2;
  int lb_k = t>>4, lb_n = (t&15)<<2;
  int tr = (t>>4)<<2, tc = (t&15)<<2;
  float acc[4][4] = {};
  for(int kt=0; kt<(K>>4); kt++){
    float4 a4;
    if(MODE==1){
      int r = row0+la_m;
      int b = r>>10, p = r&1023, i = p>>5, j = p&31;
      int k = (kt<<4)+la_k;
      int seg = k>>8, ic = k&255;
      int tok = ((2*i + (seg>>1))<<6) + 2*j + (seg&1);
      a4 = *(const float4*)(A + (size_t)((b<<12)+tok)*256 + ic);
    } else {
      a4 = *(const float4*)(A + (size_t)(row0+la_m)*K + (kt<<4)+la_k);
    }
    float4 b4 = *(const float4*)(B + (size_t)((kt<<4)+lb_k)*Nn + col0+lb_n);
    __syncthreads();
    sA[la_k][la_m]=a4.x; sA[la_k+1][la_m]=a4.y;
    sA[la_k+2][la_m]=a4.z; sA[la_k+3][la_m]=a4.w;
    *(float4*)&sB[lb_k][lb_n] = b4;
    __syncthreads();
    #pragma unroll
    for(int kk=0;kk<16;kk++){
      float4 av=*(const float4*)&sA[kk][tr];
      float4 bv=*(const float4*)&sB[kk][tc];
      float ar[4]={av.x,av.y,av.z,av.w}, br[4]={bv.x,bv.y,bv.z,bv.w};
      #pragma unroll
      for(int i=0;i<4;i++)
        #pragma unroll
        for(int j=0;j<4;j++) acc[i][j] = fmaf(ar[i],br[j],acc[i][j]);
    }
  }
  #pragma unroll
  for(int i=0;i<4;i++){
    int r = row0+tr+i;
    float4 v4;
    v4.x = acc[i][0]+bi[col0+tc+0];
    v4.y = acc[i][1]+bi[col0+tc+1];
    v4.z = acc[i][2]+bi[col0+tc+2];
    v4.w = acc[i][3]+bi[col0+tc+3];
    *(float4*)&C[(size_t)r*Nn + col0+tc] = v4;
  }
}

// fused: blocks [0,768) = mode0 big (128x6 tiles), [768,1024) = mode1 (64x4)
__global__ void gemm01_k(const float* __restrict__ x, const float* __restrict__ srb){
  int bid = blockIdx.x;
  if(bid < 768) gemm_big<0>(x, g_Wcat, g_bcat, g_proj1, bid/6, bid%6);
  else { int b2 = bid-768; gemm_body<1>(x, g_srwT, srb, g_xs_pre, b2>>2, b2&3); }
}
__global__ void gemm2_k(const float* __restrict__ kv1w, const float* __restrict__ kv1b){
  gemm_body<2>(g_xs, kv1w, kv1b, g_kv1, blockIdx.x>>2, blockIdx.x&3);
}
__global__ void gemm3_k(const float* __restrict__ pw, const float* __restrict__ pb,
                        float* __restrict__ out){
  gemm_big<3>(g_pre, pw, pb, out, blockIdx.x>>1, blockIdx.x&1);
}

// ---------------- LayerNorm + exact GELU ------------------------------------
__global__ void ln_gelu_k(const float* __restrict__ nw, const float* __restrict__ nb){
  int r = blockIdx.x, c = threadIdx.x;
  float v = g_xs_pre[(size_t)r*256+c];
  float s = v, s2 = v*v;
  #pragma unroll
  for(int o=16;o;o>>=1){ s += __shfl_xor_sync(~0u,s,o); s2 += __shfl_xor_sync(~0u,s2,o); }
  __shared__ float rs[8], rs2[8];
  int w = c>>5, l = c&31;
  if(l==0){ rs[w]=s; rs2[w]=s2; }
  __syncthreads();
  if(w==0){
    float a=(l<8)?rs[l]:0.f, a2=(l<8)?rs2[l]:0.f;
    #pragma unroll
    for(int o=4;o;o>>=1){ a+=__shfl_xor_sync(~0u,a,o); a2+=__shfl_xor_sync(~0u,a2,o); }
    if(l==0){ rs[0]=a; rs2[0]=a2; }
  }
  __syncthreads();
  float m  = rs[0]*(1.f/256.f);
  float var= rs2[0]*(1.f/256.f) - m*m;
  float y  = (v-m)*rsqrtf(var+1e-5f)*nw[c] + nb[c];
  g_xs[(size_t)r*256+c] = 0.5f*y*(1.f+erff(y*0.70710678118f));
}

// ---------------- branch-1 attention (R9-proven) -----------------------------
// grid (128 qtiles, 4 heads, 4 batch), 256 threads
extern __shared__ float dsm[];
__global__ void attn1_k(){
  float* sS  = dsm;               // 33024 floats
  float* sQ  = sS + 33024;        // 1152
  float* sKV = sQ + 1152;         // 2 * 4608
  int t = threadIdx.x;
  int qt = blockIdx.x, h = blockIdx.y, b = blockIdx.z;
  int n0 = qt*32;
  int fm[4], fd[4];
  #pragma unroll
  for(int r=0;r<4;r++){ int e = t + 256*r; fm[r] = e>>3; fd[r] = (e&7)<<2; }
  size_t kvbase = (size_t)(b<<10)*256;

  {
    int q = t>>3, d4 = (t&7)<<2;
    *(float4*)&sQ[q*36+d4] =
      *(const float4*)&g_proj1[((size_t)(b*4096+n0+q))*768 + h*32 + d4];
  }
  float4 pf[4];
  #pragma unroll
  for(int r=0;r<4;r++)
    pf[r] = *(const float4*)&g_kv1[kvbase + (size_t)fm[r]*256 + h*32 + fd[r]];
  __syncthreads();
  #pragma unroll
  for(int r=0;r<4;r++) *(float4*)&sKV[fm[r]*36 + fd[r]] = pf[r];
  __syncthreads();

  // ---- scores ----
  int qb = t>>5, kb = t&31;
  for(int kt=0;kt<8;kt++){
    float* buf = sKV + (kt&1)*4608;
    if(kt<7){
      #pragma unroll
      for(int r=0;r<4;r++)
        pf[r] = *(const float4*)&g_kv1[kvbase + (size_t)(((kt+1)<<7)+fm[r])*256 + h*32 + fd[r]];
    }
    float acc[4][4] = {};
    #pragma unroll
    for(int d4=0; d4<8; d4++){
      float4 qv[4], kv[4];
      #pragma unroll
      for(int i=0;i<4;i++) qv[i] = *(const float4*)&sQ[(qb*4+i)*36 + (d4<<2)];
      #pragma unroll
      for(int u=0;u<4;u++) kv[u] = *(const float4*)&buf[(kb+32*u)*36 + (d4<<2)];
      #pragma unroll
      for(int i=0;i<4;i++)
        #pragma unroll
        for(int u=0;u<4;u++){
          acc[i][u] = fmaf(qv[i].x, kv[u].x, acc[i][u]);
          acc[i][u] = fmaf(qv[i].y, kv[u].y, acc[i][u]);
          acc[i][u] = fmaf(qv[i].z, kv[u].z, acc[i][u]);
          acc[i][u] = fmaf(qv[i].w, kv[u].w, acc[i][u]);
        }
    }
    int m0 = kt<<7;
    #pragma unroll
    for(int i=0;i<4;i++)
      #pragma unroll
      for(int u=0;u<4;u++)
        sS[(qb*4+i)*1032 + m0 + kb + 32*u] = acc[i][u]*SCALE1;
    if(kt<7){
      float* nbuf = sKV + ((kt+1)&1)*4608;
      #pragma unroll
      for(int r=0;r<4;r++) *(float4*)&nbuf[fm[r]*36 + fd[r]] = pf[r];
    }
    __syncthreads();
  }

  // prefetch V tile 0 (hidden under softmax)
  #pragma unroll
  for(int r=0;r<4;r++)
    pf[r] = *(const float4*)&g_kv1[kvbase + (size_t)fm[r]*256 + 128 + h*32 + fd[r]];

  // ---- softmax ----
  {
    int w = t>>5, l = t&31;
    for(int qi=0;qi<4;qi++){
      float4* row4 = (float4*)(sS + (w*4+qi)*1032);
      float mx = -1e30f;
      #pragma unroll
      for(int i2=0;i2<8;i2++){
        float4 v = row4[l + 32*i2];
        mx = fmaxf(mx, fmaxf(fmaxf(v.x,v.y), fmaxf(v.z,v.w)));
      }
      mx = wredmax(mx);
      float sm = 0.f;
      #pragma unroll
      for(int i2=0;i2<8;i2++){
        float4 v = row4[l + 32*i2];
        v.x = __expf(v.x-mx); v.y = __expf(v.y-mx);
        v.z = __expf(v.z-mx); v.w = __expf(v.w-mx);
        row4[l+32*i2] = v;
        sm += (v.x+v.y)+(v.z+v.w);
      }
      sm = wredsum(sm);
      float inv = 1.f/sm;
      #pragma unroll
      for(int i2=0;i2<8;i2++){
        float4 v = row4[l+32*i2];
        v.x*=inv; v.y*=inv; v.z*=inv; v.w*=inv;
        row4[l+32*i2] = v;
      }
    }
  }
  #pragma unroll
  for(int r=0;r<4;r++) *(float4*)&sKV[fm[r]*36 + fd[r]] = pf[r];
  __syncthreads();

  // ---- per-key partial sums for g ----
  {
    float4 s4 = make_float4(0.f,0.f,0.f,0.f);
    #pragma unroll 8
    for(int q=0;q<32;q++){
      float4 v = *(const float4*)&sS[q*1032 + t*4];
      s4.x+=v.x; s4.y+=v.y; s4.z+=v.z; s4.w+=v.w;
    }
    *(float4*)&g_part[((size_t)(b*512 + h*128 + qt))*1024 + t*4] = s4;
  }

  // ---- AV ----
  int kq = t>>5;
  int qr = (t>>2)&7;
  int dr = t&3;
  float accv[4][8];
  #pragma unroll
  for(int i=0;i<4;i++)
    #pragma unroll
    for(int u=0;u<8;u++) accv[i][u] = 0.f;
  for(int kt=0;kt<8;kt++){
    float* buf = sKV + (kt&1)*4608;
    if(kt<7){
      #pragma unroll
      for(int r=0;r<4;r++)
        pf[r] = *(const float4*)&g_kv1[kvbase + (size_t)(((kt+1)<<7)+fm[r])*256 + 128 + h*32 + fd[r]];
    }
    int m0 = kt<<7;
    #pragma unroll
    for(int j4=0;j4<4;j4++){
      float4 p[4];
      #pragma unroll
      for(int i=0;i<4;i++)
        p[i] = *(const float4*)&sS[(qr*4+i)*1032 + m0 + kq*16 + j4*4];
      #pragma unroll
      for(int jj=0;jj<4;jj++){
        int mm = kq*16 + j4*4 + jj;
        float4 v0 = *(const float4*)&buf[mm*36 + dr*8];
        float4 v1 = *(const float4*)&buf[mm*36 + dr*8 + 4];
        float pv[4] = { ((const float*)&p[0])[jj], ((const float*)&p[1])[jj],
                        ((const float*)&p[2])[jj], ((const float*)&p[3])[jj] };
        #pragma unroll
        for(int i=0;i<4;i++){
          accv[i][0] = fmaf(pv[i], v0.x, accv[i][0]);
          accv[i][1] = fmaf(pv[i], v0.y, accv[i][1]);
          accv[i][2] = fmaf(pv[i], v0.z, accv[i][2]);
          accv[i][3] = fmaf(pv[i], v0.w, accv[i][3]);
          accv[i][4] = fmaf(pv[i], v1.x, accv[i][4]);
          accv[i][5] = fmaf(pv[i], v1.y, accv[i][5]);
          accv[i][6] = fmaf(pv[i], v1.z, accv[i][6]);
          accv[i][7] = fmaf(pv[i], v1.w, accv[i][7]);
        }
      }
    }
    if(kt<7){
      float* nbuf = sKV + ((kt+1)&1)*4608;
      #pragma unroll
      for(int r=0;r<4;r++) *(float4*)&nbuf[fm[r]*36 + fd[r]] = pf[r];
    }
    __syncthreads();
  }
  #pragma unroll
  for(int i=0;i<4;i++){
    float* dst = sS + kq*1024 + (qr*4+i)*32 + dr*8;
    *(float4*)&dst[0] = make_float4(accv[i][0],accv[i][1],accv[i][2],accv[i][3]);
    *(float4*)&dst[4] = make_float4(accv[i][4],accv[i][5],accv[i][6],accv[i][7]);
  }
  __syncthreads();
  {
    float4 s4 = make_float4(0.f,0.f,0.f,0.f);
    #pragma unroll
    for(int g=0; g<8; g++){
      float4 v = *(const float4*)&sS[g*1024 + t*4];
      s4.x+=v.x; s4.y+=v.y; s4.z+=v.z; s4.w+=v.w;
    }
    int oi = t*4;
    int q = oi>>5, dd = oi&31;
    *(float4*)&g_cat[((size_t)(b*4096+n0+q))*256 + h*32 + dd] = s4;
  }
}

// ---------------- g reduction (64 blocks, deterministic) ---------------------
__global__ void gred_k(){
  int b = blockIdx.x>>4;
  int ml = threadIdx.x&63;
  int pg = threadIdx.x>>6;
  int m = (blockIdx.x&15)*64 + ml;
  float s = 0.f;
  for(int p=pg; p<512; p+=4)
    s += g_part[((size_t)(b*512+p))*1024 + m];
  __shared__ float red[4][64];
  red[pg][ml] = s;
  __syncthreads();
  if(pg==0)
    g_gsum[b*1024+m] = (red[0][ml]+red[1][ml])+(red[2][ml]+red[3][ml]);
}

// ---------------- branch-2 window attention ----------------------------------
__global__ void attn2_k(){
  __shared__ float sQ[4][16][33], sK[4][16][33], sV[4][16][33];
  __shared__ float sS[4][16][17];
  int t = threadIdx.x;
  int win = blockIdx.x, b = blockIdx.y;
  int i1 = win>>4, j1 = win&15;
  for(int e=t;e<2048;e+=256){
    int h=e>>9, rem=e&511, tk=rem>>5, dd=rem&31;
    int n = ((i1*4 + (tk>>2))<<6) + j1*4 + (tk&3);
    size_t base = ((size_t)(b*4096+n))*768 + h*32+dd;
    sQ[h][tk][dd] = g_proj1[base+128];
    sK[h][tk][dd] = g_proj1[base+256];
    sV[h][tk][dd] = g_proj1[base+384];
  }
  __syncthreads();
  int h = t>>6, q = (t>>2)&15, kg = t&3;
  #pragma unroll
  for(int k2=0;k2<4;k2++){
    int kk = kg*4+k2;
    float s = 0.f;
    #pragma unroll
    for(int dd=0;dd<32;dd++) s = fmaf(sQ[h][q][dd], sK[h][kk][dd], s);
    sS[h][q][kk] = s*SCALE1;
  }
  __syncthreads();
  if(kg==0){
    float* row = sS[h][q];
    float mx=-1e30f;
    #pragma unroll
    for(int kk=0;kk<16;kk++) mx = fmaxf(mx,row[kk]);
    float sm=0.f;
    #pragma unroll
    for(int kk=0;kk<16;kk++){ float p=__expf(row[kk]-mx); row[kk]=p; sm+=p; }
    float inv=1.f/sm;
    #pragma unroll
    for(int kk=0;kk<16;kk++) row[kk]*=inv;
  }
  __syncthreads();
  float acc[8]={};
  int dd0 = kg*8;
  #pragma unroll
  for(int kk=0;kk<16;kk++){
    float p = sS[h][q][kk];
    #pragma unroll
    for(int u=0;u<8;u++) acc[u] = fmaf(p, sV[h][kk][dd0+u], acc[u]);
  }
  {
    int n = ((i1*4+(q>>2))<<6) + j1*4 + (q&3);
    float* dst = &g_cat[((size_t)(b*4096+n))*256 + 128 + h*32 + dd0];
    #pragma unroll
    for(int u=0;u<8;u++) dst[u] = acc[u];
  }
  if(t<16){
    float s=0.f;
    #pragma unroll
    for(int h2=0;h2<4;h2++)
      #pragma unroll
      for(int q2=0;q2<16;q2++) s += sS[h2][q2][t];
    int y = i1*4 + (t>>2), x = j1*4 + (t&3);
    g_lm[b*4096 + y*64 + x] = s*(1.f/64.f);
  }
}

// ---------------- depthwise lepe conv + concat add ---------------------------
__global__ void lepe_k(const float* __restrict__ lcb){
  int blk = blockIdx.x, c = threadIdx.x;
  int b = blk>>12, pos = blk&4095, y = pos>>6, x = pos&63;
  float acc = lcb[c];
  #pragma unroll
  for(int dy=-1;dy<=1;dy++){
    int yy = y+dy; if((unsigned)yy >= 64u) continue;
    #pragma unroll
    for(int dx=-1;dx<=1;dx++){
      int xx = x+dx; if((unsigned)xx >= 64u) continue;
      int tap = (dy+1)*3 + (dx+1);
      acc = fmaf(g_proj1[((size_t)(b*4096 + yy*64+xx))*768 + 512 + c],
                 g_lwT[tap*256+c], acc);
    }
  }
  size_t o = (size_t)blk*256 + c;
  g_pre[o] = g_cat[o] + acc;
}

// ---------------- mask assembly ----------------------------------------------
__global__ void mask_k(float* __restrict__ out){
  int idx = blockIdx.x*256 + threadIdx.x;      // 0..16383
  int b = idx>>12, pos = idx&4095, y = pos>>6, x = pos&63;
  float v = g_lm[idx] + g_gsum[b*1024 + (y>>1)*32 + (x>>1)] * (1.f/16384.f);
  out[4194304 + idx] = v;                       // mask1 [b, y*64+x]
  out[4210688 + b*4096 + x*64 + y] = v;         // mask2 [b, x*64+y]
}

// ---------------- launch -----------------------------------------------------
extern "C" void kernel_launch(void* const* d_in, const int* in_sizes, int n_in,
                              void* d_out, int out_size)
{
  const float* x    = (const float*)d_in[0];
  const float* q1w  = (const float*)d_in[1];
  const float* q1b  = (const float*)d_in[2];
  const float* kv1w = (const float*)d_in[3];
  const float* kv1b = (const float*)d_in[4];
  const float* q2w  = (const float*)d_in[5];
  const float* q2b  = (const float*)d_in[6];
  const float* kv2w = (const float*)d_in[7];
  const float* kv2b = (const float*)d_in[8];
  const float* lpw  = (const float*)d_in[9];
  const float* lpb  = (const float*)d_in[10];
  const float* lcw  = (const float*)d_in[11];
  const float* lcb  = (const float*)d_in[12];
  const float* srw  = (const float*)d_in[13];
  const float* srb  = (const float*)d_in[14];
  const float* nw   = (const float*)d_in[15];
  const float* nb   = (const float*)d_in[16];
  const float* pw   = (const float*)d_in[17];
  const float* pb   = (const float*)d_in[18];
  float* out = (float*)d_out;

  const int ATTN1_SMEM = (33024 + 1152 + 2*4608) * 4;  // 173568 B
  cudaFuncSetAttribute(attn1_k, cudaFuncAttributeMaxDynamicSharedMemorySize, ATTN1_SMEM);

  prep_k<<<256,256>>>(q1w,q2w,kv2w,lpw,q1b,q2b,kv2b,lpb,srw,lcw);
  nop_k<<<1,32>>>();
  nop_k<<<1,32>>>();
  gemm01_k<<<1024,256>>>(x, srb);                // proj1(big,FFMA2) + xs_pre; profiled slot
  attn2_k<<<dim3(256,4),256>>>();
  ln_gelu_k<<<4096,256>>>(nw, nb);
  gemm2_k<<<256,256>>>(kv1w, kv1b);              // kv1
  attn1_k<<<dim3(128,4,4), 256, ATTN1_SMEM>>>();
  gred_k<<<64,256>>>();
  lepe_k<<<16384,256>>>(lcb);
  gemm3_k<<<256,256>>>(pw, pb, out);             // proj(big,FFMA2) -> out
  mask_k<<<64,256>>>(out);
}

// round 13
// speedup vs baseline: 2.0559x; 1.0842x over previous
#include <cuda_runtime.h>
#include <cuda_bf16.h>
#include <math.h>

#define SCALE1 0.17677669529663687f  // 32^-0.5
typedef __nv_bfloat16 bf16;

// ---------------- scratch (static device globals; no allocation) ------------
__device__ float g_proj1[16384*768];   // [q1 | q2 | kv2(k,v) | lepe_lin]
__device__ float g_xs_pre[4096*256];
__device__ float g_kv1[4096*256];
__device__ float g_cat[16384*256];     // [x1 | x2]
__device__ float g_part[4*512*1024];
__device__ float g_gsum[4*1024];
__device__ float g_lm[4*4096];
__device__ float g_bcat[768];
__device__ float g_lwT[9*256];         // (tap, c)
// bf16 hi/lo-split operands: A'' = [hi|lo|hi], B'' = [hi|hi|lo]
__device__ bf16  g_xhl[16384*768];     // x split
__device__ bf16  g_prehl[16384*768];   // (cat+lepe) split
__device__ bf16  g_xshl[4096*768];     // gelu(ln(xs)) split
__device__ bf16  g_WcatB[768*768];     // [n][k'']
__device__ bf16  g_srwB[256*3072];     // [n][k''] for SR conv (K=1024 -> 3072)
__device__ bf16  g_pwB[256*768];
__device__ bf16  g_kv1B[256*768];

// ---------------- helpers ---------------------------------------------------
__device__ __forceinline__ float wredmax(float v){
  #pragma unroll
  for(int o=16;o;o>>=1) v = fmaxf(v, __shfl_xor_sync(0xFFFFFFFFu, v, o));
  return v;
}
__device__ __forceinline__ float wredsum(float v){
  #pragma unroll
  for(int o=16;o;o>>=1) v += __shfl_xor_sync(0xFFFFFFFFu, v, o);
  return v;
}
__device__ __forceinline__ void mma_bf16(float4& c, const unsigned a[4], const unsigned b[2]){
  asm("mma.sync.aligned.m16n8k16.row.col.f32.bf16.bf16.f32 "
      "{%0,%1,%2,%3}, {%4,%5,%6,%7}, {%8,%9}, {%0,%1,%2,%3};"
      : "+f"(c.x), "+f"(c.y), "+f"(c.z), "+f"(c.w)
      : "r"(a[0]), "r"(a[1]), "r"(a[2]), "r"(a[3]), "r"(b[0]), "r"(b[1]));
}
__device__ __forceinline__ void split2(float v, bf16& hi, bf16& lo){
  hi = __float2bfloat16(v);
  lo = __float2bfloat16(v - __bfloat162float(hi));
}

__global__ void nop_k(){}

// ---------------- weight prep ------------------------------------------------
__global__ void prep_k(const float* __restrict__ q1w, const float* __restrict__ q2w,
                       const float* __restrict__ kv2w, const float* __restrict__ lpw,
                       const float* __restrict__ q1b, const float* __restrict__ q2b,
                       const float* __restrict__ kv2b, const float* __restrict__ lpb,
                       const float* __restrict__ srw, const float* __restrict__ lcw,
                       const float* __restrict__ kv1w, const float* __restrict__ pw)
{
  int i0 = blockIdx.x*blockDim.x + threadIdx.x;
  int st = gridDim.x*blockDim.x;
  for(int c=i0;c<768;c+=st)
    g_bcat[c] = (c<128)?q1b[c]:(c<256)?q2b[c-128]:(c<512)?kv2b[c-256]:lpb[c-512];
  for(int idx=i0; idx<9*256; idx+=st){
    int tap = idx>>8, c = idx&255;
    g_lwT[idx] = lcw[c*9+tap];
  }
  // WcatB [n=768][k''=768]
  for(int idx=i0; idx<768*256; idx+=st){
    int n = idx>>8, k = idx&255;
    float w = (n<128)? q1w[k*128+n] : (n<256)? q2w[k*128+(n-128)]
            : (n<512)? kv2w[k*256+(n-256)] : lpw[k*256+(n-512)];
    bf16 hi, lo; split2(w, hi, lo);
    g_WcatB[n*768 + k]       = hi;
    g_WcatB[n*768 + 256 + k] = hi;
    g_WcatB[n*768 + 512 + k] = lo;
  }
  // srwB [n=256][k''=3072], inner k = seg*256+ic, w = srw[(n*256+ic)*4+seg]
  for(int idx=i0; idx<256*1024; idx+=st){
    int n = idx>>10, k = idx&1023;
    float w = srw[(n*256 + (k&255))*4 + (k>>8)];
    bf16 hi, lo; split2(w, hi, lo);
    g_srwB[n*3072 + k]        = hi;
    g_srwB[n*3072 + 1024 + k] = hi;
    g_srwB[n*3072 + 2048 + k] = lo;
  }
  // pwB / kv1B [n=256][k''=768]
  for(int idx=i0; idx<256*256; idx+=st){
    int n = idx>>8, k = idx&255;
    bf16 hi, lo;
    split2(pw[k*256+n], hi, lo);
    g_pwB[n*768+k] = hi; g_pwB[n*768+256+k] = hi; g_pwB[n*768+512+k] = lo;
    split2(kv1w[k*256+n], hi, lo);
    g_kv1B[n*768+k] = hi; g_kv1B[n*768+256+k] = hi; g_kv1B[n*768+512+k] = lo;
  }
}

// ---------------- x -> hi/lo split -------------------------------------------
__global__ void convx_k(const float* __restrict__ x){
  int m = blockIdx.x, c = threadIdx.x;
  float v = x[(size_t)m*256+c];
  bf16 hi, lo; split2(v, hi, lo);
  size_t b = (size_t)m*768;
  g_xhl[b+c] = hi; g_xhl[b+256+c] = lo; g_xhl[b+512+c] = hi;
}

// ---------------- bf16-split MMA GEMM, 128x128 block, 256 thr ----------------
// MODE 0: g_xhl   @ g_WcatB (K''=768, N=768) +g_bcat -> g_proj1
// MODE 1: gather(g_xhl) @ g_srwB (K''=3072, N=256) +srb -> g_xs_pre
// MODE 2: g_xshl  @ g_kv1B (768, 256) +kv1b -> g_kv1
// MODE 3: g_prehl @ g_pwB  (768, 256) +pb, x2 -> d_out
template<int MODE>
__device__ __forceinline__ void gemm_mma(const bf16* __restrict__ Ag,
                                         const bf16* __restrict__ Bg,
                                         const float* __restrict__ bi,
                                         float* __restrict__ C,
                                         int by, int bx)
{
  constexpr int K2 = (MODE==1)?3072:768;
  constexpr int Nn = (MODE==0)?768:256;
  __shared__ __align__(16) bf16 sA[128*72];
  __shared__ __align__(16) bf16 sB[128*72];
  int t = threadIdx.x;
  int m0 = by*128, n0 = bx*128;
  int wid = t>>5, lane = t&31;
  int wm = wid>>1, wn = wid&1;
  int g = lane>>2, tg = lane&3;
  float4 acc[2][8];
  #pragma unroll
  for(int i=0;i<2;i++)
    #pragma unroll
    for(int j=0;j<8;j++) acc[i][j] = make_float4(0.f,0.f,0.f,0.f);

  for(int kc=0; kc<K2/64; kc++){
    __syncthreads();
    #pragma unroll
    for(int i=0;i<4;i++){
      int e = t + (i<<8);
      int r = e>>3, c8 = e&7;
      const bf16* ap;
      if constexpr (MODE==1){
        int gr = m0 + r;
        int bb = gr>>10, p = gr&1023, ii = p>>5, jj = p&31;
        int s   = kc>>4;        // hi/lo/hi segment
        int seg = (kc>>2)&3;    // conv tap
        int ic0 = (kc&3)*64;
        int tok = (bb<<12) + ((2*ii + (seg>>1))<<6) + 2*jj + (seg&1);
        ap = Ag + (size_t)tok*768 + s*256 + ic0 + c8*8;
      } else {
        ap = Ag + (size_t)(m0+r)*K2 + kc*64 + c8*8;
      }
      *(uint4*)&sA[r*72 + c8*8] = *(const uint4*)ap;
      *(uint4*)&sB[r*72 + c8*8] =
        *(const uint4*)(Bg + (size_t)(n0+r)*K2 + kc*64 + c8*8);
    }
    __syncthreads();
    #pragma unroll
    for(int ks=0; ks<4; ks++){
      unsigned a[2][4], b[8][2];
      #pragma unroll
      for(int mt=0;mt<2;mt++){
        const bf16* base = sA + (wm*32 + mt*16 + g)*72 + ks*16;
        a[mt][0] = *(const unsigned*)(base + 2*tg);
        a[mt][1] = *(const unsigned*)(base + 8*72 + 2*tg);
        a[mt][2] = *(const unsigned*)(base + 2*tg + 8);
        a[mt][3] = *(const unsigned*)(base + 8*72 + 2*tg + 8);
      }
      #pragma unroll
      for(int nt=0;nt<8;nt++){
        const bf16* base = sB + (wn*64 + nt*8 + g)*72 + ks*16;
        b[nt][0] = *(const unsigned*)(base + 2*tg);
        b[nt][1] = *(const unsigned*)(base + 2*tg + 8);
      }
      #pragma unroll
      for(int mt=0;mt<2;mt++)
        #pragma unroll
        for(int nt=0;nt<8;nt++) mma_bf16(acc[mt][nt], a[mt], b[nt]);
    }
  }
  #pragma unroll
  for(int mt=0;mt<2;mt++){
    int r0 = m0 + wm*32 + mt*16 + g;
    #pragma unroll
    for(int nt=0;nt<8;nt++){
      int c0 = n0 + wn*64 + nt*8 + 2*tg;
      float2 v0 = make_float2(acc[mt][nt].x + bi[c0], acc[mt][nt].y + bi[c0+1]);
      float2 v1 = make_float2(acc[mt][nt].z + bi[c0], acc[mt][nt].w + bi[c0+1]);
      if(MODE==3){ v0.x*=2.f; v0.y*=2.f; v1.x*=2.f; v1.y*=2.f; }
      *(float2*)&C[(size_t)r0*Nn + c0]     = v0;
      *(float2*)&C[(size_t)(r0+8)*Nn + c0] = v1;
    }
  }
}

// fused: blocks [0,768) = mode0 (128x6), [768,832) = mode1 (32x2)
__global__ void gemm01_k(const float* __restrict__ srb){
  int bid = blockIdx.x;
  if(bid < 768) gemm_mma<0>(g_xhl, g_WcatB, g_bcat, g_proj1, bid/6, bid%6);
  else { int b2 = bid-768; gemm_mma<1>(g_xhl, g_srwB, srb, g_xs_pre, b2>>1, b2&1); }
}
__global__ void gemm2_k(const float* __restrict__ kv1b){
  gemm_mma<2>(g_xshl, g_kv1B, kv1b, g_kv1, blockIdx.x>>1, blockIdx.x&1);
}
__global__ void gemm3_k(const float* __restrict__ pb, float* __restrict__ out){
  gemm_mma<3>(g_prehl, g_pwB, pb, out, blockIdx.x>>1, blockIdx.x&1);
}

// ---------------- LayerNorm + exact GELU -> hi/lo split ----------------------
__global__ void ln_gelu_k(const float* __restrict__ nw, const float* __restrict__ nb){
  int r = blockIdx.x, c = threadIdx.x;
  float v = g_xs_pre[(size_t)r*256+c];
  float s = v, s2 = v*v;
  #pragma unroll
  for(int o=16;o;o>>=1){ s += __shfl_xor_sync(~0u,s,o); s2 += __shfl_xor_sync(~0u,s2,o); }
  __shared__ float rs[8], rs2[8];
  int w = c>>5, l = c&31;
  if(l==0){ rs[w]=s; rs2[w]=s2; }
  __syncthreads();
  if(w==0){
    float a=(l<8)?rs[l]:0.f, a2=(l<8)?rs2[l]:0.f;
    #pragma unroll
    for(int o=4;o;o>>=1){ a+=__shfl_xor_sync(~0u,a,o); a2+=__shfl_xor_sync(~0u,a2,o); }
    if(l==0){ rs[0]=a; rs2[0]=a2; }
  }
  __syncthreads();
  float m  = rs[0]*(1.f/256.f);
  float var= rs2[0]*(1.f/256.f) - m*m;
  float y  = (v-m)*rsqrtf(var+1e-5f)*nw[c] + nb[c];
  float gv = 0.5f*y*(1.f+erff(y*0.70710678118f));
  bf16 hi, lo; split2(gv, hi, lo);
  size_t b = (size_t)r*768;
  g_xshl[b+c] = hi; g_xshl[b+256+c] = lo; g_xshl[b+512+c] = hi;
}

// ---------------- branch-1 attention (R9-proven, fp32) -----------------------
extern __shared__ float dsm[];
__global__ void attn1_k(){
  float* sS  = dsm;               // 33024 floats
  float* sQ  = sS + 33024;        // 1152
  float* sKV = sQ + 1152;         // 2 * 4608
  int t = threadIdx.x;
  int qt = blockIdx.x, h = blockIdx.y, b = blockIdx.z;
  int n0 = qt*32;
  int fm[4], fd[4];
  #pragma unroll
  for(int r=0;r<4;r++){ int e = t + 256*r; fm[r] = e>>3; fd[r] = (e&7)<<2; }
  size_t kvbase = (size_t)(b<<10)*256;

  {
    int q = t>>3, d4 = (t&7)<<2;
    *(float4*)&sQ[q*36+d4] =
      *(const float4*)&g_proj1[((size_t)(b*4096+n0+q))*768 + h*32 + d4];
  }
  float4 pf[4];
  #pragma unroll
  for(int r=0;r<4;r++)
    pf[r] = *(const float4*)&g_kv1[kvbase + (size_t)fm[r]*256 + h*32 + fd[r]];
  __syncthreads();
  #pragma unroll
  for(int r=0;r<4;r++) *(float4*)&sKV[fm[r]*36 + fd[r]] = pf[r];
  __syncthreads();

  int qb = t>>5, kb = t&31;
  for(int kt=0;kt<8;kt++){
    float* buf = sKV + (kt&1)*4608;
    if(kt<7){
      #pragma unroll
      for(int r=0;r<4;r++)
        pf[r] = *(const float4*)&g_kv1[kvbase + (size_t)(((kt+1)<<7)+fm[r])*256 + h*32 + fd[r]];
    }
    float acc[4][4] = {};
    #pragma unroll
    for(int d4=0; d4<8; d4++){
      float4 qv[4], kv[4];
      #pragma unroll
      for(int i=0;i<4;i++) qv[i] = *(const float4*)&sQ[(qb*4+i)*36 + (d4<<2)];
      #pragma unroll
      for(int u=0;u<4;u++) kv[u] = *(const float4*)&buf[(kb+32*u)*36 + (d4<<2)];
      #pragma unroll
      for(int i=0;i<4;i++)
        #pragma unroll
        for(int u=0;u<4;u++){
          acc[i][u] = fmaf(qv[i].x, kv[u].x, acc[i][u]);
          acc[i][u] = fmaf(qv[i].y, kv[u].y, acc[i][u]);
          acc[i][u] = fmaf(qv[i].z, kv[u].z, acc[i][u]);
          acc[i][u] = fmaf(qv[i].w, kv[u].w, acc[i][u]);
        }
    }
    int m0 = kt<<7;
    #pragma unroll
    for(int i=0;i<4;i++)
      #pragma unroll
      for(int u=0;u<4;u++)
        sS[(qb*4+i)*1032 + m0 + kb + 32*u] = acc[i][u]*SCALE1;
    if(kt<7){
      float* nbuf = sKV + ((kt+1)&1)*4608;
      #pragma unroll
      for(int r=0;r<4;r++) *(float4*)&nbuf[fm[r]*36 + fd[r]] = pf[r];
    }
    __syncthreads();
  }

  #pragma unroll
  for(int r=0;r<4;r++)
    pf[r] = *(const float4*)&g_kv1[kvbase + (size_t)fm[r]*256 + 128 + h*32 + fd[r]];

  {
    int w = t>>5, l = t&31;
    for(int qi=0;qi<4;qi++){
      float4* row4 = (float4*)(sS + (w*4+qi)*1032);
      float mx = -1e30f;
      #pragma unroll
      for(int i2=0;i2<8;i2++){
        float4 v = row4[l + 32*i2];
        mx = fmaxf(mx, fmaxf(fmaxf(v.x,v.y), fmaxf(v.z,v.w)));
      }
      mx = wredmax(mx);
      float sm = 0.f;
      #pragma unroll
      for(int i2=0;i2<8;i2++){
        float4 v = row4[l + 32*i2];
        v.x = __expf(v.x-mx); v.y = __expf(v.y-mx);
        v.z = __expf(v.z-mx); v.w = __expf(v.w-mx);
        row4[l+32*i2] = v;
        sm += (v.x+v.y)+(v.z+v.w);
      }
      sm = wredsum(sm);
      float inv = 1.f/sm;
      #pragma unroll
      for(int i2=0;i2<8;i2++){
        float4 v = row4[l+32*i2];
        v.x*=inv; v.y*=inv; v.z*=inv; v.w*=inv;
        row4[l+32*i2] = v;
      }
    }
  }
  #pragma unroll
  for(int r=0;r<4;r++) *(float4*)&sKV[fm[r]*36 + fd[r]] = pf[r];
  __syncthreads();

  {
    float4 s4 = make_float4(0.f,0.f,0.f,0.f);
    #pragma unroll 8
    for(int q=0;q<32;q++){
      float4 v = *(const float4*)&sS[q*1032 + t*4];
      s4.x+=v.x; s4.y+=v.y; s4.z+=v.z; s4.w+=v.w;
    }
    *(float4*)&g_part[((size_t)(b*512 + h*128 + qt))*1024 + t*4] = s4;
  }

  int kq = t>>5;
  int qr = (t>>2)&7;
  int dr = t&3;
  float accv[4][8];
  #pragma unroll
  for(int i=0;i<4;i++)
    #pragma unroll
    for(int u=0;u<8;u++) accv[i][u] = 0.f;
  for(int kt=0;kt<8;kt++){
    float* buf = sKV + (kt&1)*4608;
    if(kt<7){
      #pragma unroll
      for(int r=0;r<4;r++)
        pf[r] = *(const float4*)&g_kv1[kvbase + (size_t)(((kt+1)<<7)+fm[r])*256 + 128 + h*32 + fd[r]];
    }
    int m0 = kt<<7;
    #pragma unroll
    for(int j4=0;j4<4;j4++){
      float4 p[4];
      #pragma unroll
      for(int i=0;i<4;i++)
        p[i] = *(const float4*)&sS[(qr*4+i)*1032 + m0 + kq*16 + j4*4];
      #pragma unroll
      for(int jj=0;jj<4;jj++){
        int mm = kq*16 + j4*4 + jj;
        float4 v0 = *(const float4*)&buf[mm*36 + dr*8];
        float4 v1 = *(const float4*)&buf[mm*36 + dr*8 + 4];
        float pv[4] = { ((const float*)&p[0])[jj], ((const float*)&p[1])[jj],
                        ((const float*)&p[2])[jj], ((const float*)&p[3])[jj] };
        #pragma unroll
        for(int i=0;i<4;i++){
          accv[i][0] = fmaf(pv[i], v0.x, accv[i][0]);
          accv[i][1] = fmaf(pv[i], v0.y, accv[i][1]);
          accv[i][2] = fmaf(pv[i], v0.z, accv[i][2]);
          accv[i][3] = fmaf(pv[i], v0.w, accv[i][3]);
          accv[i][4] = fmaf(pv[i], v1.x, accv[i][4]);
          accv[i][5] = fmaf(pv[i], v1.y, accv[i][5]);
          accv[i][6] = fmaf(pv[i], v1.z, accv[i][6]);
          accv[i][7] = fmaf(pv[i], v1.w, accv[i][7]);
        }
      }
    }
    if(kt<7){
      float* nbuf = sKV + ((kt+1)&1)*4608;
      #pragma unroll
      for(int r=0;r<4;r++) *(float4*)&nbuf[fm[r]*36 + fd[r]] = pf[r];
    }
    __syncthreads();
  }
  #pragma unroll
  for(int i=0;i<4;i++){
    float* dst = sS + kq*1024 + (qr*4+i)*32 + dr*8;
    *(float4*)&dst[0] = make_float4(accv[i][0],accv[i][1],accv[i][2],accv[i][3]);
    *(float4*)&dst[4] = make_float4(accv[i][4],accv[i][5],accv[i][6],accv[i][7]);
  }
  __syncthreads();
  {
    float4 s4 = make_float4(0.f,0.f,0.f,0.f);
    #pragma unroll
    for(int g2=0; g2<8; g2++){
      float4 v = *(const float4*)&sS[g2*1024 + t*4];
      s4.x+=v.x; s4.y+=v.y; s4.z+=v.z; s4.w+=v.w;
    }
    int oi = t*4;
    int q = oi>>5, dd = oi&31;
    *(float4*)&g_cat[((size_t)(b*4096+n0+q))*256 + h*32 + dd] = s4;
  }
}

// ---------------- g reduction -------------------------------------------------
__global__ void gred_k(){
  int b = blockIdx.x>>4;
  int ml = threadIdx.x&63;
  int pg = threadIdx.x>>6;
  int m = (blockIdx.x&15)*64 + ml;
  float s = 0.f;
  for(int p=pg; p<512; p+=4)
    s += g_part[((size_t)(b*512+p))*1024 + m];
  __shared__ float red[4][64];
  red[pg][ml] = s;
  __syncthreads();
  if(pg==0)
    g_gsum[b*1024+m] = (red[0][ml]+red[1][ml])+(red[2][ml]+red[3][ml]);
}

// ---------------- branch-2 window attention ----------------------------------
__global__ void attn2_k(){
  __shared__ float sQ[4][16][33], sK[4][16][33], sV[4][16][33];
  __shared__ float sS[4][16][17];
  int t = threadIdx.x;
  int win = blockIdx.x, b = blockIdx.y;
  int i1 = win>>4, j1 = win&15;
  for(int e=t;e<2048;e+=256){
    int h=e>>9, rem=e&511, tk=rem>>5, dd=rem&31;
    int n = ((i1*4 + (tk>>2))<<6) + j1*4 + (tk&3);
    size_t base = ((size_t)(b*4096+n))*768 + h*32+dd;
    sQ[h][tk][dd] = g_proj1[base+128];
    sK[h][tk][dd] = g_proj1[base+256];
    sV[h][tk][dd] = g_proj1[base+384];
  }
  __syncthreads();
  int h = t>>6, q = (t>>2)&15, kg = t&3;
  #pragma unroll
  for(int k2=0;k2<4;k2++){
    int kk = kg*4+k2;
    float s = 0.f;
    #pragma unroll
    for(int dd=0;dd<32;dd++) s = fmaf(sQ[h][q][dd], sK[h][kk][dd], s);
    sS[h][q][kk] = s*SCALE1;
  }
  __syncthreads();
  if(kg==0){
    float* row = sS[h][q];
    float mx=-1e30f;
    #pragma unroll
    for(int kk=0;kk<16;kk++) mx = fmaxf(mx,row[kk]);
    float sm=0.f;
    #pragma unroll
    for(int kk=0;kk<16;kk++){ float p=__expf(row[kk]-mx); row[kk]=p; sm+=p; }
    float inv=1.f/sm;
    #pragma unroll
    for(int kk=0;kk<16;kk++) row[kk]*=inv;
  }
  __syncthreads();
  float acc[8]={};
  int dd0 = kg*8;
  #pragma unroll
  for(int kk=0;kk<16;kk++){
    float p = sS[h][q][kk];
    #pragma unroll
    for(int u=0;u<8;u++) acc[u] = fmaf(p, sV[h][kk][dd0+u], acc[u]);
  }
  {
    int n = ((i1*4+(q>>2))<<6) + j1*4 + (q&3);
    float* dst = &g_cat[((size_t)(b*4096+n))*256 + 128 + h*32 + dd0];
    #pragma unroll
    for(int u=0;u<8;u++) dst[u] = acc[u];
  }
  if(t<16){
    float s=0.f;
    #pragma unroll
    for(int h2=0;h2<4;h2++)
      #pragma unroll
      for(int q2=0;q2<16;q2++) s += sS[h2][q2][t];
    int y = i1*4 + (t>>2), x = j1*4 + (t&3);
    g_lm[b*4096 + y*64 + x] = s*(1.f/64.f);
  }
}

// ---------------- depthwise lepe conv + concat add -> hi/lo split ------------
__global__ void lepe_k(const float* __restrict__ lcb){
  int blk = blockIdx.x, c = threadIdx.x;
  int b = blk>>12, pos = blk&4095, y = pos>>6, x = pos&63;
  float acc = lcb[c];
  #pragma unroll
  for(int dy=-1;dy<=1;dy++){
    int yy = y+dy; if((unsigned)yy >= 64u) continue;
    #pragma unroll
    for(int dx=-1;dx<=1;dx++){
      int xx = x+dx; if((unsigned)xx >= 64u) continue;
      int tap = (dy+1)*3 + (dx+1);
      acc = fmaf(g_proj1[((size_t)(b*4096 + yy*64+xx))*768 + 512 + c],
                 g_lwT[tap*256+c], acc);
    }
  }
  float v = g_cat[(size_t)blk*256 + c] + acc;
  bf16 hi, lo; split2(v, hi, lo);
  size_t o = (size_t)blk*768;
  g_prehl[o+c] = hi; g_prehl[o+256+c] = lo; g_prehl[o+512+c] = hi;
}

// ---------------- mask assembly ----------------------------------------------
__global__ void mask_k(float* __restrict__ out){
  int idx = blockIdx.x*256 + threadIdx.x;
  int b = idx>>12, pos = idx&4095, y = pos>>6, x = pos&63;
  float v = g_lm[idx] + g_gsum[b*1024 + (y>>1)*32 + (x>>1)] * (1.f/16384.f);
  out[4194304 + idx] = v;
  out[4210688 + b*4096 + x*64 + y] = v;
}

// ---------------- launch -----------------------------------------------------
extern "C" void kernel_launch(void* const* d_in, const int* in_sizes, int n_in,
                              void* d_out, int out_size)
{
  const float* x    = (const float*)d_in[0];
  const float* q1w  = (const float*)d_in[1];
  const float* q1b  = (const float*)d_in[2];
  const float* kv1w = (const float*)d_in[3];
  const float* kv1b = (const float*)d_in[4];
  const float* q2w  = (const float*)d_in[5];
  const float* q2b  = (const float*)d_in[6];
  const float* kv2w = (const float*)d_in[7];
  const float* kv2b = (const float*)d_in[8];
  const float* lpw  = (const float*)d_in[9];
  const float* lpb  = (const float*)d_in[10];
  const float* lcw  = (const float*)d_in[11];
  const float* lcb  = (const float*)d_in[12];
  const float* srw  = (const float*)d_in[13];
  const float* srb  = (const float*)d_in[14];
  const float* nw   = (const float*)d_in[15];
  const float* nb   = (const float*)d_in[16];
  const float* pw   = (const float*)d_in[17];
  const float* pb   = (const float*)d_in[18];
  float* out = (float*)d_out;

  const int ATTN1_SMEM = (33024 + 1152 + 2*4608) * 4;  // 173568 B
  cudaFuncSetAttribute(attn1_k, cudaFuncAttributeMaxDynamicSharedMemorySize, ATTN1_SMEM);

  prep_k<<<256,256>>>(q1w,q2w,kv2w,lpw,q1b,q2b,kv2b,lpb,srw,lcw,kv1w,pw);
  convx_k<<<16384,256>>>(x);
  nop_k<<<1,32>>>();
  gemm01_k<<<832,256>>>(srb);                    // proj1 + xs_pre (bf16-split MMA); profiled slot
  attn2_k<<<dim3(256,4),256>>>();
  ln_gelu_k<<<4096,256>>>(nw, nb);
  gemm2_k<<<64,256>>>(kv1b);                     // kv1 (MMA)
  attn1_k<<<dim3(128,4,4), 256, ATTN1_SMEM>>>();
  gred_k<<<64,256>>>();
  lepe_k<<<16384,256>>>(lcb);
  gemm3_k<<<256,256>>>(pb, out);                 // proj (MMA) -> out
  mask_k<<<64,256>>>(out);
}

// round 14
// speedup vs baseline: 2.1892x; 1.0649x over previous
#include <cuda_runtime.h>
#include <cuda_bf16.h>
#include <math.h>

#define SCALE1 0.17677669529663687f  // 32^-0.5
typedef __nv_bfloat16 bf16;

// ---------------- scratch (static device globals; no allocation) ------------
__device__ float g_proj1[16384*768];   // [q1 | q2 | kv2(k,v) | lepe_lin]
__device__ float g_xs_pre[4096*256];
__device__ float g_kv1[4096*256];
__device__ float g_cat[16384*256];     // [x1 | x2]
__device__ float g_part[4*512*1024];
__device__ float g_gsum[4*1024];
__device__ float g_lm[4*4096];
__device__ float g_bcat[768];
__device__ float g_lwT[9*256];         // (tap, c)
// bf16 hi/lo-split operands: A'' = [hi|lo|hi], B'' = [hi|hi|lo]
__device__ bf16  g_xhl[16384*768];     // x split
__device__ bf16  g_prehl[16384*768];   // (cat+lepe) split
__device__ bf16  g_xshl[4096*768];     // gelu(ln(xs)) split
__device__ bf16  g_WcatB[768*768];     // [n][k'']
__device__ bf16  g_srwB[256*3072];     // [n][k''] for SR conv (K=1024 -> 3072)
__device__ bf16  g_pwB[256*768];
__device__ bf16  g_kv1B[256*768];

// ---------------- helpers ---------------------------------------------------
__device__ __forceinline__ float wredmax(float v){
  #pragma unroll
  for(int o=16;o;o>>=1) v = fmaxf(v, __shfl_xor_sync(0xFFFFFFFFu, v, o));
  return v;
}
__device__ __forceinline__ float wredsum(float v){
  #pragma unroll
  for(int o=16;o;o>>=1) v += __shfl_xor_sync(0xFFFFFFFFu, v, o);
  return v;
}
__device__ __forceinline__ void mma_bf16(float4& c, const unsigned a[4], const unsigned b0, const unsigned b1){
  asm("mma.sync.aligned.m16n8k16.row.col.f32.bf16.bf16.f32 "
      "{%0,%1,%2,%3}, {%4,%5,%6,%7}, {%8,%9}, {%0,%1,%2,%3};"
      : "+f"(c.x), "+f"(c.y), "+f"(c.z), "+f"(c.w)
      : "r"(a[0]), "r"(a[1]), "r"(a[2]), "r"(a[3]), "r"(b0), "r"(b1));
}
__device__ __forceinline__ void split2(float v, bf16& hi, bf16& lo){
  hi = __float2bfloat16(v);
  lo = __float2bfloat16(v - __bfloat162float(hi));
}
__device__ __forceinline__ unsigned sm_u32(const void* p){
  return (unsigned)__cvta_generic_to_shared(p);
}
__device__ __forceinline__ void ldsm_x4(unsigned r[4], unsigned addr){
  asm volatile("ldmatrix.sync.aligned.m8n8.x4.shared.b16 {%0,%1,%2,%3}, [%4];"
    : "=r"(r[0]),"=r"(r[1]),"=r"(r[2]),"=r"(r[3]) : "r"(addr));
}
__device__ __forceinline__ void cpa16(unsigned saddr, const void* g){
  asm volatile("cp.async.cg.shared.global [%0], [%1], 16;" :: "r"(saddr), "l"(g));
}

__global__ void nop_k(){}

// ---------------- weight prep ------------------------------------------------
__global__ void prep_k(const float* __restrict__ q1w, const float* __restrict__ q2w,
                       const float* __restrict__ kv2w, const float* __restrict__ lpw,
                       const float* __restrict__ q1b, const float* __restrict__ q2b,
                       const float* __restrict__ kv2b, const float* __restrict__ lpb,
                       const float* __restrict__ srw, const float* __restrict__ lcw,
                       const float* __restrict__ kv1w, const float* __restrict__ pw)
{
  int i0 = blockIdx.x*blockDim.x + threadIdx.x;
  int st = gridDim.x*blockDim.x;
  for(int c=i0;c<768;c+=st)
    g_bcat[c] = (c<128)?q1b[c]:(c<256)?q2b[c-128]:(c<512)?kv2b[c-256]:lpb[c-512];
  for(int idx=i0; idx<9*256; idx+=st){
    int tap = idx>>8, c = idx&255;
    g_lwT[idx] = lcw[c*9+tap];
  }
  for(int idx=i0; idx<768*256; idx+=st){
    int n = idx>>8, k = idx&255;
    float w = (n<128)? q1w[k*128+n] : (n<256)? q2w[k*128+(n-128)]
            : (n<512)? kv2w[k*256+(n-256)] : lpw[k*256+(n-512)];
    bf16 hi, lo; split2(w, hi, lo);
    g_WcatB[n*768 + k]       = hi;
    g_WcatB[n*768 + 256 + k] = hi;
    g_WcatB[n*768 + 512 + k] = lo;
  }
  for(int idx=i0; idx<256*1024; idx+=st){
    int n = idx>>10, k = idx&1023;
    float w = srw[(n*256 + (k&255))*4 + (k>>8)];
    bf16 hi, lo; split2(w, hi, lo);
    g_srwB[n*3072 + k]        = hi;
    g_srwB[n*3072 + 1024 + k] = hi;
    g_srwB[n*3072 + 2048 + k] = lo;
  }
  for(int idx=i0; idx<256*256; idx+=st){
    int n = idx>>8, k = idx&255;
    bf16 hi, lo;
    split2(pw[k*256+n], hi, lo);
    g_pwB[n*768+k] = hi; g_pwB[n*768+256+k] = hi; g_pwB[n*768+512+k] = lo;
    split2(kv1w[k*256+n], hi, lo);
    g_kv1B[n*768+k] = hi; g_kv1B[n*768+256+k] = hi; g_kv1B[n*768+512+k] = lo;
  }
}

// ---------------- x -> hi/lo split -------------------------------------------
__global__ void convx_k(const float* __restrict__ x){
  int m = blockIdx.x, c = threadIdx.x;
  float v = x[(size_t)m*256+c];
  bf16 hi, lo; split2(v, hi, lo);
  size_t b = (size_t)m*768;
  g_xhl[b+c] = hi; g_xhl[b+256+c] = lo; g_xhl[b+512+c] = hi;
}

// ---------------- bf16-split MMA GEMM: ldmatrix + cp.async double-buffer -----
// 128x128 block, 256 thr; dynamic smem 2*(128*72)*2 bf16 tiles for A and B.
extern __shared__ float dsm[];
template<int MODE>
__device__ __forceinline__ void gemm_mma(const bf16* __restrict__ Ag,
                                         const bf16* __restrict__ Bg,
                                         const float* __restrict__ bi,
                                         float* __restrict__ C,
                                         int by, int bx)
{
  constexpr int K2 = (MODE==1)?3072:768;
  constexpr int Nn = (MODE==0)?768:256;
  constexpr int NKC = K2/64;
  bf16* sAb = (bf16*)dsm;                 // sA[2][128*72]
  bf16* sBb = sAb + 2*128*72;             // sB[2][128*72]
  int t = threadIdx.x;
  int m0 = by*128, n0 = bx*128;
  int wid = t>>5, lane = t&31;
  int wm = wid>>1, wn = wid&1;
  int g = lane>>2, tg = lane&3;
  int lane15 = lane&15, lk8 = ((lane>>4)&1)*8;
  float4 acc[2][8];
  #pragma unroll
  for(int i=0;i<2;i++)
    #pragma unroll
    for(int j=0;j<8;j++) acc[i][j] = make_float4(0.f,0.f,0.f,0.f);

  auto issue_tile = [&](int kc, int s){
    bf16* sA = sAb + s*(128*72);
    bf16* sB = sBb + s*(128*72);
    #pragma unroll
    for(int i=0;i<4;i++){
      int e = t + (i<<8);
      int r = e>>3, c8 = e&7;
      const bf16* ap;
      if constexpr (MODE==1){
        int gr = m0 + r;
        int bb = gr>>10, p = gr&1023, ii = p>>5, jj = p&31;
        int sseg = kc>>4;       // hi/lo/hi segment
        int seg  = (kc>>2)&3;   // conv tap
        int ic0  = (kc&3)*64;
        int tok = (bb<<12) + ((2*ii + (seg>>1))<<6) + 2*jj + (seg&1);
        ap = Ag + (size_t)tok*768 + sseg*256 + ic0 + c8*8;
      } else {
        ap = Ag + (size_t)(m0+r)*K2 + kc*64 + c8*8;
      }
      cpa16(sm_u32(&sA[r*72 + c8*8]), ap);
      cpa16(sm_u32(&sB[r*72 + c8*8]), Bg + (size_t)(n0+r)*K2 + kc*64 + c8*8);
    }
    asm volatile("cp.async.commit_group;" ::: "memory");
  };

  issue_tile(0, 0);
  for(int kc=0; kc<NKC; kc++){
    int s = kc&1;
    bf16* sA = sAb + s*(128*72);
    bf16* sB = sBb + s*(128*72);
    asm volatile("cp.async.wait_group 0;" ::: "memory");
    __syncthreads();
    if(kc+1 < NKC) issue_tile(kc+1, s^1);
    #pragma unroll
    for(int ks=0; ks<4; ks++){
      unsigned a[2][4], bq[4][4];
      #pragma unroll
      for(int mt=0;mt<2;mt++)
        ldsm_x4(a[mt], sm_u32(&sA[(wm*32 + mt*16 + lane15)*72 + ks*16 + lk8]));
      #pragma unroll
      for(int p=0;p<4;p++)
        ldsm_x4(bq[p], sm_u32(&sB[(wn*64 + p*16 + lane15)*72 + ks*16 + lk8]));
      #pragma unroll
      for(int mt=0;mt<2;mt++)
        #pragma unroll
        for(int nt=0;nt<8;nt++)
          mma_bf16(acc[mt][nt], a[mt], bq[nt>>1][nt&1], bq[nt>>1][2+(nt&1)]);
    }
    __syncthreads();
  }
  #pragma unroll
  for(int mt=0;mt<2;mt++){
    int r0 = m0 + wm*32 + mt*16 + g;
    #pragma unroll
    for(int nt=0;nt<8;nt++){
      int c0 = n0 + wn*64 + nt*8 + 2*tg;
      float2 v0 = make_float2(acc[mt][nt].x + bi[c0], acc[mt][nt].y + bi[c0+1]);
      float2 v1 = make_float2(acc[mt][nt].z + bi[c0], acc[mt][nt].w + bi[c0+1]);
      if(MODE==3){ v0.x*=2.f; v0.y*=2.f; v1.x*=2.f; v1.y*=2.f; }
      *(float2*)&C[(size_t)r0*Nn + c0]     = v0;
      *(float2*)&C[(size_t)(r0+8)*Nn + c0] = v1;
    }
  }
}

#define GEMM_SMEM (4*128*72*2)  // 73728 B

// fused: blocks [0,768) = mode0 (128x6), [768,832) = mode1 (32x2)
__global__ void __launch_bounds__(256,2) gemm01_k(const float* __restrict__ srb){
  int bid = blockIdx.x;
  if(bid < 768) gemm_mma<0>(g_xhl, g_WcatB, g_bcat, g_proj1, bid/6, bid%6);
  else { int b2 = bid-768; gemm_mma<1>(g_xhl, g_srwB, srb, g_xs_pre, b2>>1, b2&1); }
}
__global__ void __launch_bounds__(256,2) gemm2_k(const float* __restrict__ kv1b){
  gemm_mma<2>(g_xshl, g_kv1B, kv1b, g_kv1, blockIdx.x>>1, blockIdx.x&1);
}
__global__ void __launch_bounds__(256,2) gemm3_k(const float* __restrict__ pb, float* __restrict__ out){
  gemm_mma<3>(g_prehl, g_pwB, pb, out, blockIdx.x>>1, blockIdx.x&1);
}

// ---------------- LayerNorm + exact GELU -> hi/lo split ----------------------
__global__ void ln_gelu_k(const float* __restrict__ nw, const float* __restrict__ nb){
  int r = blockIdx.x, c = threadIdx.x;
  float v = g_xs_pre[(size_t)r*256+c];
  float s = v, s2 = v*v;
  #pragma unroll
  for(int o=16;o;o>>=1){ s += __shfl_xor_sync(~0u,s,o); s2 += __shfl_xor_sync(~0u,s2,o); }
  __shared__ float rs[8], rs2[8];
  int w = c>>5, l = c&31;
  if(l==0){ rs[w]=s; rs2[w]=s2; }
  __syncthreads();
  if(w==0){
    float a=(l<8)?rs[l]:0.f, a2=(l<8)?rs2[l]:0.f;
    #pragma unroll
    for(int o=4;o;o>>=1){ a+=__shfl_xor_sync(~0u,a,o); a2+=__shfl_xor_sync(~0u,a2,o); }
    if(l==0){ rs[0]=a; rs2[0]=a2; }
  }
  __syncthreads();
  float m  = rs[0]*(1.f/256.f);
  float var= rs2[0]*(1.f/256.f) - m*m;
  float y  = (v-m)*rsqrtf(var+1e-5f)*nw[c] + nb[c];
  float gv = 0.5f*y*(1.f+erff(y*0.70710678118f));
  bf16 hi, lo; split2(gv, hi, lo);
  size_t b = (size_t)r*768;
  g_xshl[b+c] = hi; g_xshl[b+256+c] = lo; g_xshl[b+512+c] = hi;
}

// ---------------- branch-1 attention (R9-proven, fp32) -----------------------
__global__ void attn1_k(){
  float* sS  = dsm;               // 33024 floats
  float* sQ  = sS + 33024;        // 1152
  float* sKV = sQ + 1152;         // 2 * 4608
  int t = threadIdx.x;
  int qt = blockIdx.x, h = blockIdx.y, b = blockIdx.z;
  int n0 = qt*32;
  int fm[4], fd[4];
  #pragma unroll
  for(int r=0;r<4;r++){ int e = t + 256*r; fm[r] = e>>3; fd[r] = (e&7)<<2; }
  size_t kvbase = (size_t)(b<<10)*256;

  {
    int q = t>>3, d4 = (t&7)<<2;
    *(float4*)&sQ[q*36+d4] =
      *(const float4*)&g_proj1[((size_t)(b*4096+n0+q))*768 + h*32 + d4];
  }
  float4 pf[4];
  #pragma unroll
  for(int r=0;r<4;r++)
    pf[r] = *(const float4*)&g_kv1[kvbase + (size_t)fm[r]*256 + h*32 + fd[r]];
  __syncthreads();
  #pragma unroll
  for(int r=0;r<4;r++) *(float4*)&sKV[fm[r]*36 + fd[r]] = pf[r];
  __syncthreads();

  int qb = t>>5, kb = t&31;
  for(int kt=0;kt<8;kt++){
    float* buf = sKV + (kt&1)*4608;
    if(kt<7){
      #pragma unroll
      for(int r=0;r<4;r++)
        pf[r] = *(const float4*)&g_kv1[kvbase + (size_t)(((kt+1)<<7)+fm[r])*256 + h*32 + fd[r]];
    }
    float acc[4][4] = {};
    #pragma unroll
    for(int d4=0; d4<8; d4++){
      float4 qv[4], kv[4];
      #pragma unroll
      for(int i=0;i<4;i++) qv[i] = *(const float4*)&sQ[(qb*4+i)*36 + (d4<<2)];
      #pragma unroll
      for(int u=0;u<4;u++) kv[u] = *(const float4*)&buf[(kb+32*u)*36 + (d4<<2)];
      #pragma unroll
      for(int i=0;i<4;i++)
        #pragma unroll
        for(int u=0;u<4;u++){
          acc[i][u] = fmaf(qv[i].x, kv[u].x, acc[i][u]);
          acc[i][u] = fmaf(qv[i].y, kv[u].y, acc[i][u]);
          acc[i][u] = fmaf(qv[i].z, kv[u].z, acc[i][u]);
          acc[i][u] = fmaf(qv[i].w, kv[u].w, acc[i][u]);
        }
    }
    int m0 = kt<<7;
    #pragma unroll
    for(int i=0;i<4;i++)
      #pragma unroll
      for(int u=0;u<4;u++)
        sS[(qb*4+i)*1032 + m0 + kb + 32*u] = acc[i][u]*SCALE1;
    if(kt<7){
      float* nbuf = sKV + ((kt+1)&1)*4608;
      #pragma unroll
      for(int r=0;r<4;r++) *(float4*)&nbuf[fm[r]*36 + fd[r]] = pf[r];
    }
    __syncthreads();
  }

  #pragma unroll
  for(int r=0;r<4;r++)
    pf[r] = *(const float4*)&g_kv1[kvbase + (size_t)fm[r]*256 + 128 + h*32 + fd[r]];

  {
    int w = t>>5, l = t&31;
    for(int qi=0;qi<4;qi++){
      float4* row4 = (float4*)(sS + (w*4+qi)*1032);
      float mx = -1e30f;
      #pragma unroll
      for(int i2=0;i2<8;i2++){
        float4 v = row4[l + 32*i2];
        mx = fmaxf(mx, fmaxf(fmaxf(v.x,v.y), fmaxf(v.z,v.w)));
      }
      mx = wredmax(mx);
      float sm = 0.f;
      #pragma unroll
      for(int i2=0;i2<8;i2++){
        float4 v = row4[l + 32*i2];
        v.x = __expf(v.x-mx); v.y = __expf(v.y-mx);
        v.z = __expf(v.z-mx); v.w = __expf(v.w-mx);
        row4[l+32*i2] = v;
        sm += (v.x+v.y)+(v.z+v.w);
      }
      sm = wredsum(sm);
      float inv = 1.f/sm;
      #pragma unroll
      for(int i2=0;i2<8;i2++){
        float4 v = row4[l+32*i2];
        v.x*=inv; v.y*=inv; v.z*=inv; v.w*=inv;
        row4[l+32*i2] = v;
      }
    }
  }
  #pragma unroll
  for(int r=0;r<4;r++) *(float4*)&sKV[fm[r]*36 + fd[r]] = pf[r];
  __syncthreads();

  {
    float4 s4 = make_float4(0.f,0.f,0.f,0.f);
    #pragma unroll 8
    for(int q=0;q<32;q++){
      float4 v = *(const float4*)&sS[q*1032 + t*4];
      s4.x+=v.x; s4.y+=v.y; s4.z+=v.z; s4.w+=v.w;
    }
    *(float4*)&g_part[((size_t)(b*512 + h*128 + qt))*1024 + t*4] = s4;
  }

  int kq = t>>5;
  int qr = (t>>2)&7;
  int dr = t&3;
  float accv[4][8];
  #pragma unroll
  for(int i=0;i<4;i++)
    #pragma unroll
    for(int u=0;u<8;u++) accv[i][u] = 0.f;
  for(int kt=0;kt<8;kt++){
    float* buf = sKV + (kt&1)*4608;
    if(kt<7){
      #pragma unroll
      for(int r=0;r<4;r++)
        pf[r] = *(const float4*)&g_kv1[kvbase + (size_t)(((kt+1)<<7)+fm[r])*256 + 128 + h*32 + fd[r]];
    }
    int m0 = kt<<7;
    #pragma unroll
    for(int j4=0;j4<4;j4++){
      float4 p[4];
      #pragma unroll
      for(int i=0;i<4;i++)
        p[i] = *(const float4*)&sS[(qr*4+i)*1032 + m0 + kq*16 + j4*4];
      #pragma unroll
      for(int jj=0;jj<4;jj++){
        int mm = kq*16 + j4*4 + jj;
        float4 v0 = *(const float4*)&buf[mm*36 + dr*8];
        float4 v1 = *(const float4*)&buf[mm*36 + dr*8 + 4];
        float pv[4] = { ((const float*)&p[0])[jj], ((const float*)&p[1])[jj],
                        ((const float*)&p[2])[jj], ((const float*)&p[3])[jj] };
        #pragma unroll
        for(int i=0;i<4;i++){
          accv[i][0] = fmaf(pv[i], v0.x, accv[i][0]);
          accv[i][1] = fmaf(pv[i], v0.y, accv[i][1]);
          accv[i][2] = fmaf(pv[i], v0.z, accv[i][2]);
          accv[i][3] = fmaf(pv[i], v0.w, accv[i][3]);
          accv[i][4] = fmaf(pv[i], v1.x, accv[i][4]);
          accv[i][5] = fmaf(pv[i], v1.y, accv[i][5]);
          accv[i][6] = fmaf(pv[i], v1.z, accv[i][6]);
          accv[i][7] = fmaf(pv[i], v1.w, accv[i][7]);
        }
      }
    }
    if(kt<7){
      float* nbuf = sKV + ((kt+1)&1)*4608;
      #pragma unroll
      for(int r=0;r<4;r++) *(float4*)&nbuf[fm[r]*36 + fd[r]] = pf[r];
    }
    __syncthreads();
  }
  #pragma unroll
  for(int i=0;i<4;i++){
    float* dst = sS + kq*1024 + (qr*4+i)*32 + dr*8;
    *(float4*)&dst[0] = make_float4(accv[i][0],accv[i][1],accv[i][2],accv[i][3]);
    *(float4*)&dst[4] = make_float4(accv[i][4],accv[i][5],accv[i][6],accv[i][7]);
  }
  __syncthreads();
  {
    float4 s4 = make_float4(0.f,0.f,0.f,0.f);
    #pragma unroll
    for(int g2=0; g2<8; g2++){
      float4 v = *(const float4*)&sS[g2*1024 + t*4];
      s4.x+=v.x; s4.y+=v.y; s4.z+=v.z; s4.w+=v.w;
    }
    int oi = t*4;
    int q = oi>>5, dd = oi&31;
    *(float4*)&g_cat[((size_t)(b*4096+n0+q))*256 + h*32 + dd] = s4;
  }
}

// ---------------- g reduction -------------------------------------------------
__global__ void gred_k(){
  int b = blockIdx.x>>4;
  int ml = threadIdx.x&63;
  int pg = threadIdx.x>>6;
  int m = (blockIdx.x&15)*64 + ml;
  float s = 0.f;
  for(int p=pg; p<512; p+=4)
    s += g_part[((size_t)(b*512+p))*1024 + m];
  __shared__ float red[4][64];
  red[pg][ml] = s;
  __syncthreads();
  if(pg==0)
    g_gsum[b*1024+m] = (red[0][ml]+red[1][ml])+(red[2][ml]+red[3][ml]);
}

// ---------------- branch-2 window attention ----------------------------------
__global__ void attn2_k(){
  __shared__ float sQ[4][16][33], sK[4][16][33], sV[4][16][33];
  __shared__ float sS[4][16][17];
  int t = threadIdx.x;
  int win = blockIdx.x, b = blockIdx.y;
  int i1 = win>>4, j1 = win&15;
  for(int e=t;e<2048;e+=256){
    int h=e>>9, rem=e&511, tk=rem>>5, dd=rem&31;
    int n = ((i1*4 + (tk>>2))<<6) + j1*4 + (tk&3);
    size_t base = ((size_t)(b*4096+n))*768 + h*32+dd;
    sQ[h][tk][dd] = g_proj1[base+128];
    sK[h][tk][dd] = g_proj1[base+256];
    sV[h][tk][dd] = g_proj1[base+384];
  }
  __syncthreads();
  int h = t>>6, q = (t>>2)&15, kg = t&3;
  #pragma unroll
  for(int k2=0;k2<4;k2++){
    int kk = kg*4+k2;
    float s = 0.f;
    #pragma unroll
    for(int dd=0;dd<32;dd++) s = fmaf(sQ[h][q][dd], sK[h][kk][dd], s);
    sS[h][q][kk] = s*SCALE1;
  }
  __syncthreads();
  if(kg==0){
    float* row = sS[h][q];
    float mx=-1e30f;
    #pragma unroll
    for(int kk=0;kk<16;kk++) mx = fmaxf(mx,row[kk]);
    float sm=0.f;
    #pragma unroll
    for(int kk=0;kk<16;kk++){ float p=__expf(row[kk]-mx); row[kk]=p; sm+=p; }
    float inv=1.f/sm;
    #pragma unroll
    for(int kk=0;kk<16;kk++) row[kk]*=inv;
  }
  __syncthreads();
  float acc[8]={};
  int dd0 = kg*8;
  #pragma unroll
  for(int kk=0;kk<16;kk++){
    float p = sS[h][q][kk];
    #pragma unroll
    for(int u=0;u<8;u++) acc[u] = fmaf(p, sV[h][kk][dd0+u], acc[u]);
  }
  {
    int n = ((i1*4+(q>>2))<<6) + j1*4 + (q&3);
    float* dst = &g_cat[((size_t)(b*4096+n))*256 + 128 + h*32 + dd0];
    #pragma unroll
    for(int u=0;u<8;u++) dst[u] = acc[u];
  }
  if(t<16){
    float s=0.f;
    #pragma unroll
    for(int h2=0;h2<4;h2++)
      #pragma unroll
      for(int q2=0;q2<16;q2++) s += sS[h2][q2][t];
    int y = i1*4 + (t>>2), x = j1*4 + (t&3);
    g_lm[b*4096 + y*64 + x] = s*(1.f/64.f);
  }
}

// ---------------- depthwise lepe conv + concat add -> hi/lo split ------------
__global__ void lepe_k(const float* __restrict__ lcb){
  int blk = blockIdx.x, c = threadIdx.x;
  int b = blk>>12, pos = blk&4095, y = pos>>6, x = pos&63;
  float acc = lcb[c];
  #pragma unroll
  for(int dy=-1;dy<=1;dy++){
    int yy = y+dy; if((unsigned)yy >= 64u) continue;
    #pragma unroll
    for(int dx=-1;dx<=1;dx++){
      int xx = x+dx; if((unsigned)xx >= 64u) continue;
      int tap = (dy+1)*3 + (dx+1);
      acc = fmaf(g_proj1[((size_t)(b*4096 + yy*64+xx))*768 + 512 + c],
                 g_lwT[tap*256+c], acc);
    }
  }
  float v = g_cat[(size_t)blk*256 + c] + acc;
  bf16 hi, lo; split2(v, hi, lo);
  size_t o = (size_t)blk*768;
  g_prehl[o+c] = hi; g_prehl[o+256+c] = lo; g_prehl[o+512+c] = hi;
}

// ---------------- mask assembly ----------------------------------------------
__global__ void mask_k(float* __restrict__ out){
  int idx = blockIdx.x*256 + threadIdx.x;
  int b = idx>>12, pos = idx&4095, y = pos>>6, x = pos&63;
  float v = g_lm[idx] + g_gsum[b*1024 + (y>>1)*32 + (x>>1)] * (1.f/16384.f);
  out[4194304 + idx] = v;
  out[4210688 + b*4096 + x*64 + y] = v;
}

// ---------------- launch -----------------------------------------------------
extern "C" void kernel_launch(void* const* d_in, const int* in_sizes, int n_in,
                              void* d_out, int out_size)
{
  const float* x    = (const float*)d_in[0];
  const float* q1w  = (const float*)d_in[1];
  const float* q1b  = (const float*)d_in[2];
  const float* kv1w = (const float*)d_in[3];
  const float* kv1b = (const float*)d_in[4];
  const float* q2w  = (const float*)d_in[5];
  const float* q2b  = (const float*)d_in[6];
  const float* kv2w = (const float*)d_in[7];
  const float* kv2b = (const float*)d_in[8];
  const float* lpw  = (const float*)d_in[9];
  const float* lpb  = (const float*)d_in[10];
  const float* lcw  = (const float*)d_in[11];
  const float* lcb  = (const float*)d_in[12];
  const float* srw  = (const float*)d_in[13];
  const float* srb  = (const float*)d_in[14];
  const float* nw   = (const float*)d_in[15];
  const float* nb   = (const float*)d_in[16];
  const float* pw   = (const float*)d_in[17];
  const float* pb   = (const float*)d_in[18];
  float* out = (float*)d_out;

  const int ATTN1_SMEM = (33024 + 1152 + 2*4608) * 4;  // 173568 B
  cudaFuncSetAttribute(attn1_k, cudaFuncAttributeMaxDynamicSharedMemorySize, ATTN1_SMEM);
  cudaFuncSetAttribute(gemm01_k, cudaFuncAttributeMaxDynamicSharedMemorySize, GEMM_SMEM);
  cudaFuncSetAttribute(gemm2_k,  cudaFuncAttributeMaxDynamicSharedMemorySize, GEMM_SMEM);
  cudaFuncSetAttribute(gemm3_k,  cudaFuncAttributeMaxDynamicSharedMemorySize, GEMM_SMEM);

  prep_k<<<256,256>>>(q1w,q2w,kv2w,lpw,q1b,q2b,kv2b,lpb,srw,lcw,kv1w,pw);
  convx_k<<<16384,256>>>(x);
  nop_k<<<1,32>>>();
  gemm01_k<<<832,256,GEMM_SMEM>>>(srb);          // proj1 + xs_pre; profiled slot
  attn2_k<<<dim3(256,4),256>>>();
  ln_gelu_k<<<4096,256>>>(nw, nb);
  gemm2_k<<<64,256,GEMM_SMEM>>>(kv1b);           // kv1
  attn1_k<<<dim3(128,4,4), 256, ATTN1_SMEM>>>();
  gred_k<<<64,256>>>();
  lepe_k<<<16384,256>>>(lcb);
  gemm3_k<<<256,256,GEMM_SMEM>>>(pb, out);       // proj -> out
  mask_k<<<64,256>>>(out);
}